// round 1
// baseline (speedup 1.0000x reference)
#include <cuda_runtime.h>
#include <math.h>

#define S_LEN   4096
#define DMODEL  768
#define NHEADS  12
#define HDIM    64

// ---------------------------------------------------------------------------
// Scratch (device globals: allocation-free per harness rules)
// ---------------------------------------------------------------------------
__device__ float g_Q[NHEADS * S_LEN * HDIM];   // [H][S][64]
__device__ float g_K[NHEADS * S_LEN * HDIM];   // [H][S][64]
__device__ float g_V[NHEADS * S_LEN * HDIM];   // [H][S][64]
__device__ float g_AO[S_LEN * DMODEL];         // attention output, [S][768]

// ---------------------------------------------------------------------------
// GEMM: C[M,N] = X[M,K] @ W[N,K]^T + bias[N]
//   M = 4096, N = K = 768.  Both X and W are K-contiguous (row-major), so
//   tiles load coalesced along K.  64x64 block tile, BK=16, 256 threads,
//   4x4 register microtile per thread.
// DST: 0->g_Q, 1->g_K, 2->g_V (head-major [H][S][64]), 3-> outp ([S][768])
// ---------------------------------------------------------------------------
template <int DST>
__global__ void __launch_bounds__(256)
gemm_proj(const float* __restrict__ Xin, const float* __restrict__ W,
          const float* __restrict__ bias, float* __restrict__ outp)
{
    __shared__ float As[16][64];
    __shared__ float Bs[16][64];

    const float* X = (DST == 3) ? (const float*)g_AO : Xin;
    float* out = (DST == 0) ? g_Q : (DST == 1) ? g_K : (DST == 2) ? g_V : outp;

    const int t  = threadIdx.x;
    const int m0 = blockIdx.x * 64;
    const int n0 = blockIdx.y * 64;
    const int ty = t >> 4;        // 0..15
    const int tx = t & 15;        // 0..15

    // loader coords: each thread loads one float4 of A and one of B per k-tile
    const int lr = t >> 2;        // row within tile, 0..63
    const int lk = (t & 3) * 4;   // k offset, {0,4,8,12}

    float c[4][4];
    #pragma unroll
    for (int i = 0; i < 4; i++)
        #pragma unroll
        for (int j = 0; j < 4; j++) c[i][j] = 0.0f;

    const float* Arow = X + (m0 + lr) * DMODEL + lk;
    const float* Brow = W + (n0 + lr) * DMODEL + lk;

    for (int k0 = 0; k0 < DMODEL; k0 += 16) {
        float4 av = *(const float4*)(Arow + k0);
        float4 bv = *(const float4*)(Brow + k0);
        As[lk + 0][lr] = av.x; As[lk + 1][lr] = av.y;
        As[lk + 2][lr] = av.z; As[lk + 3][lr] = av.w;
        Bs[lk + 0][lr] = bv.x; Bs[lk + 1][lr] = bv.y;
        Bs[lk + 2][lr] = bv.z; Bs[lk + 3][lr] = bv.w;
        __syncthreads();

        #pragma unroll
        for (int kk = 0; kk < 16; kk++) {
            float a[4], b[4];
            #pragma unroll
            for (int i = 0; i < 4; i++) a[i] = As[kk][ty * 4 + i];
            #pragma unroll
            for (int j = 0; j < 4; j++) b[j] = Bs[kk][tx * 4 + j];
            #pragma unroll
            for (int i = 0; i < 4; i++)
                #pragma unroll
                for (int j = 0; j < 4; j++) c[i][j] += a[i] * b[j];
        }
        __syncthreads();
    }

    #pragma unroll
    for (int i = 0; i < 4; i++) {
        const int row = m0 + ty * 4 + i;
        #pragma unroll
        for (int j = 0; j < 4; j++) {
            const int col = n0 + tx * 4 + j;
            const float v = c[i][j] + bias[col];
            if (DST < 3) {
                // head-major: [head][seq][hd]
                out[(col >> 6) * (S_LEN * HDIM) + row * HDIM + (col & 63)] = v;
            } else {
                out[row * DMODEL + col] = v;
            }
        }
    }
}

// ---------------------------------------------------------------------------
// Causal flash attention.
// grid = (S/64 q-tiles, NHEADS), block = 256 threads.
// Dynamic smem: Qs[64][64] | Ks[64][65] | Vs[64][65] | Ps[64][65]
// Online softmax, 4x4 register microtiles for both S=QK^T and O=PV.
// ---------------------------------------------------------------------------
#define ATTN_SMEM_FLOATS (64*64 + 3*64*65)
#define ATTN_SMEM_BYTES  (ATTN_SMEM_FLOATS * 4)

__global__ void __launch_bounds__(256)
attn_kernel()
{
    extern __shared__ float sh[];
    float* Qs = sh;                 // stride 64 (broadcast-only access)
    float* Ks = Qs + 64 * 64;       // stride 65
    float* Vs = Ks + 64 * 65;       // stride 65
    float* Ps = Vs + 64 * 65;       // stride 65
    __shared__ float row_m[64], row_l[64], row_scale[64];

    const int h  = blockIdx.y;
    const int qt = blockIdx.x;
    const int t  = threadIdx.x;
    const int ty = t >> 4, tx = t & 15;
    const int tq = ty * 4, tk = tx * 4;

    const float* Qg = g_Q + (h * S_LEN + qt * 64) * HDIM;

    // load Q tile (stride-64 smem, conflict-free: 16 thr/row write consecutive)
    #pragma unroll
    for (int i = 0; i < 4; i++) {
        const int idx = t + i * 256;
        const int r = idx >> 4, cg = (idx & 15) * 4;
        float4 v = *(const float4*)(Qg + r * 64 + cg);
        Qs[r * 64 + cg + 0] = v.x; Qs[r * 64 + cg + 1] = v.y;
        Qs[r * 64 + cg + 2] = v.z; Qs[r * 64 + cg + 3] = v.w;
    }
    if (t < 64) { row_m[t] = -1e30f; row_l[t] = 0.0f; }

    float o[4][4];
    #pragma unroll
    for (int i = 0; i < 4; i++)
        #pragma unroll
        for (int j = 0; j < 4; j++) o[i][j] = 0.0f;

    __syncthreads();

    for (int kt = 0; kt <= qt; kt++) {
        const float* Kg = g_K + (h * S_LEN + kt * 64) * HDIM;
        const float* Vg = g_V + (h * S_LEN + kt * 64) * HDIM;
        #pragma unroll
        for (int i = 0; i < 4; i++) {
            const int idx = t + i * 256;
            const int r = idx >> 4, cg = (idx & 15) * 4;
            float4 kv = *(const float4*)(Kg + r * 64 + cg);
            Ks[r * 65 + cg + 0] = kv.x; Ks[r * 65 + cg + 1] = kv.y;
            Ks[r * 65 + cg + 2] = kv.z; Ks[r * 65 + cg + 3] = kv.w;
            float4 vv = *(const float4*)(Vg + r * 64 + cg);
            Vs[r * 65 + cg + 0] = vv.x; Vs[r * 65 + cg + 1] = vv.y;
            Vs[r * 65 + cg + 2] = vv.z; Vs[r * 65 + cg + 3] = vv.w;
        }
        __syncthreads();

        // S = Q . K^T  (4x4 microtile)
        float acc[4][4];
        #pragma unroll
        for (int i = 0; i < 4; i++)
            #pragma unroll
            for (int j = 0; j < 4; j++) acc[i][j] = 0.0f;

        #pragma unroll 8
        for (int d = 0; d < 64; d++) {
            float a[4], b[4];
            #pragma unroll
            for (int i = 0; i < 4; i++) a[i] = Qs[(tq + i) * 64 + d];
            #pragma unroll
            for (int j = 0; j < 4; j++) b[j] = Ks[(tk + j) * 65 + d];
            #pragma unroll
            for (int i = 0; i < 4; i++)
                #pragma unroll
                for (int j = 0; j < 4; j++) acc[i][j] += a[i] * b[j];
        }

        const bool diag = (kt == qt);
        #pragma unroll
        for (int i = 0; i < 4; i++)
            #pragma unroll
            for (int j = 0; j < 4; j++) {
                float s = acc[i][j] * 0.125f;   // 1/sqrt(64)
                if (diag && (tk + j) > (tq + i)) s = -1e30f;
                Ps[(tq + i) * 65 + tk + j] = s;
            }
        __syncthreads();

        // online softmax stats (one thread per row; bank-conflict-free: stride 65)
        if (t < 64) {
            float* pr = Ps + t * 65;
            const float m_old = row_m[t];
            float m = m_old;
            #pragma unroll 8
            for (int c2 = 0; c2 < 64; c2++) m = fmaxf(m, pr[c2]);
            const float sc = __expf(m_old - m);
            float sum = 0.0f;
            #pragma unroll 8
            for (int c2 = 0; c2 < 64; c2++) {
                const float p = __expf(pr[c2] - m);
                pr[c2] = p;
                sum += p;
            }
            row_l[t] = row_l[t] * sc + sum;
            row_m[t] = m;
            row_scale[t] = sc;
        }
        __syncthreads();

        // rescale + O += P . V  (4x4 microtile)
        #pragma unroll
        for (int i = 0; i < 4; i++) {
            const float sc = row_scale[tq + i];
            #pragma unroll
            for (int j = 0; j < 4; j++) o[i][j] *= sc;
        }
        #pragma unroll 8
        for (int k = 0; k < 64; k++) {
            float p[4], v[4];
            #pragma unroll
            for (int i = 0; i < 4; i++) p[i] = Ps[(tq + i) * 65 + k];
            #pragma unroll
            for (int j = 0; j < 4; j++) v[j] = Vs[k * 65 + tk + j];
            #pragma unroll
            for (int i = 0; i < 4; i++)
                #pragma unroll
                for (int j = 0; j < 4; j++) o[i][j] += p[i] * v[j];
        }
        __syncthreads();
    }

    // finalize: divide by l, write to [S][768] with column h*64+hd
    #pragma unroll
    for (int i = 0; i < 4; i++) {
        const float inv = 1.0f / row_l[tq + i];
        const int srow = qt * 64 + tq + i;
        #pragma unroll
        for (int j = 0; j < 4; j++) {
            g_AO[srow * DMODEL + h * HDIM + tk + j] = o[i][j] * inv;
        }
    }
}

// ---------------------------------------------------------------------------
// Launch
// ---------------------------------------------------------------------------
extern "C" void kernel_launch(void* const* d_in, const int* in_sizes, int n_in,
                              void* d_out, int out_size)
{
    const float* x  = (const float*)d_in[0];
    const float* Wq = (const float*)d_in[1];
    const float* bq = (const float*)d_in[2];
    const float* Wk = (const float*)d_in[3];
    const float* bk = (const float*)d_in[4];
    const float* Wv = (const float*)d_in[5];
    const float* bv = (const float*)d_in[6];
    const float* Wo = (const float*)d_in[7];
    const float* bo = (const float*)d_in[8];
    float* out = (float*)d_out;

    cudaFuncSetAttribute(attn_kernel,
                         cudaFuncAttributeMaxDynamicSharedMemorySize,
                         ATTN_SMEM_BYTES);

    dim3 gg(S_LEN / 64, DMODEL / 64);   // 64 x 12
    dim3 gb(256);

    gemm_proj<0><<<gg, gb>>>(x, Wq, bq, nullptr);
    gemm_proj<1><<<gg, gb>>>(x, Wk, bk, nullptr);
    gemm_proj<2><<<gg, gb>>>(x, Wv, bv, nullptr);

    dim3 ag(S_LEN / 64, NHEADS);        // 64 x 12
    attn_kernel<<<ag, 256, ATTN_SMEM_BYTES>>>();

    gemm_proj<3><<<gg, gb>>>(nullptr, Wo, bo, out);
}

// round 2
// speedup vs baseline: 2.0003x; 2.0003x over previous
#include <cuda_runtime.h>
#include <stdint.h>
#include <math.h>

#define S_LEN   4096
#define DMODEL  768
#define NHEADS  12
#define HDIM    64

// ---------------------------------------------------------------------------
// Scratch (device globals)
// ---------------------------------------------------------------------------
__device__ float g_Q[NHEADS * S_LEN * HDIM];   // [H][S][64] (tf32-rounded)
__device__ float g_K[NHEADS * S_LEN * HDIM];
__device__ float g_V[NHEADS * S_LEN * HDIM];
__device__ float g_AO[S_LEN * DMODEL];         // attention output [S][768]

// ---------------------------------------------------------------------------
// TF32 helpers
// ---------------------------------------------------------------------------
__device__ __forceinline__ uint32_t f2tf(float x) {
    uint32_t r;
    asm("cvt.rna.tf32.f32 %0, %1;" : "=r"(r) : "f"(x));
    return r;
}
__device__ __forceinline__ float f2tf_f(float x) {
    return __uint_as_float(f2tf(x));
}

// mma.sync m16n8k8 tf32, fp32 accumulate
__device__ __forceinline__ void mma8(float c[4], const uint32_t a[4], const uint32_t b[2]) {
    asm volatile(
        "mma.sync.aligned.m16n8k8.row.col.f32.tf32.tf32.f32 "
        "{%0,%1,%2,%3},{%4,%5,%6,%7},{%8,%9},{%0,%1,%2,%3};"
        : "+f"(c[0]), "+f"(c[1]), "+f"(c[2]), "+f"(c[3])
        : "r"(a[0]), "r"(a[1]), "r"(a[2]), "r"(a[3]), "r"(b[0]), "r"(b[1]));
}

// ---------------------------------------------------------------------------
// Projection GEMM, 3xTF32: C[M,N] = X[M,K] @ W[N,K]^T + bias
// Block tile 128x64, K-step 32, 8 warps (4m x 2n), warp tile 32x32.
// DST: 0->g_Q, 1->g_K, 2->g_V (head-major), 3->outp ([S][768])
// ---------------------------------------------------------------------------
template <int DST>
__global__ void __launch_bounds__(256)
gemm_tc(const float* __restrict__ Xin, const float* __restrict__ W,
        const float* __restrict__ bias, float* __restrict__ outp)
{
    __shared__ float Xs[128][36];
    __shared__ float Ws[64][36];

    const float* X = (DST == 3) ? (const float*)g_AO : Xin;
    float* out = (DST == 0) ? g_Q : (DST == 1) ? g_K : (DST == 2) ? g_V : outp;

    const int t    = threadIdx.x;
    const int lane = t & 31;
    const int wid  = t >> 5;
    const int m0   = blockIdx.x * 128;
    const int n0   = blockIdx.y * 64;
    const int wm   = (wid & 3) * 32;   // warp row offset in block
    const int wn   = (wid >> 2) * 32;  // warp col offset in block
    const int lr   = lane >> 2;        // 0..7
    const int lc   = lane & 3;         // 0..3

    float c[2][4][4];
    #pragma unroll
    for (int mt = 0; mt < 2; mt++)
        #pragma unroll
        for (int nt = 0; nt < 4; nt++)
            #pragma unroll
            for (int q = 0; q < 4; q++) c[mt][nt][q] = 0.0f;

    for (int k0 = 0; k0 < DMODEL; k0 += 32) {
        // load X tile 128x32 (1024 float4)
        #pragma unroll
        for (int i = 0; i < 4; i++) {
            const int idx = t + i * 256;
            const int r = idx >> 3, cg = (idx & 7) * 4;
            float4 v = *(const float4*)(X + (m0 + r) * DMODEL + k0 + cg);
            Xs[r][cg + 0] = v.x; Xs[r][cg + 1] = v.y;
            Xs[r][cg + 2] = v.z; Xs[r][cg + 3] = v.w;
        }
        // load W tile 64x32 (512 float4)
        #pragma unroll
        for (int i = 0; i < 2; i++) {
            const int idx = t + i * 256;
            const int r = idx >> 3, cg = (idx & 7) * 4;
            float4 v = *(const float4*)(W + (n0 + r) * DMODEL + k0 + cg);
            Ws[r][cg + 0] = v.x; Ws[r][cg + 1] = v.y;
            Ws[r][cg + 2] = v.z; Ws[r][cg + 3] = v.w;
        }
        __syncthreads();

        #pragma unroll
        for (int ks = 0; ks < 32; ks += 8) {
            const int kc = ks + lc;
            uint32_t ah[2][4], al[2][4], bh[4][2], bl[4][2];
            #pragma unroll
            for (int mt = 0; mt < 2; mt++) {
                const int r = wm + mt * 16 + lr;
                float x0 = Xs[r][kc],     x1 = Xs[r + 8][kc];
                float x2 = Xs[r][kc + 4], x3 = Xs[r + 8][kc + 4];
                ah[mt][0] = f2tf(x0); al[mt][0] = f2tf(x0 - __uint_as_float(ah[mt][0]));
                ah[mt][1] = f2tf(x1); al[mt][1] = f2tf(x1 - __uint_as_float(ah[mt][1]));
                ah[mt][2] = f2tf(x2); al[mt][2] = f2tf(x2 - __uint_as_float(ah[mt][2]));
                ah[mt][3] = f2tf(x3); al[mt][3] = f2tf(x3 - __uint_as_float(ah[mt][3]));
            }
            #pragma unroll
            for (int nt = 0; nt < 4; nt++) {
                const int n = wn + nt * 8 + lr;
                float w0 = Ws[n][kc], w1 = Ws[n][kc + 4];
                bh[nt][0] = f2tf(w0); bl[nt][0] = f2tf(w0 - __uint_as_float(bh[nt][0]));
                bh[nt][1] = f2tf(w1); bl[nt][1] = f2tf(w1 - __uint_as_float(bh[nt][1]));
            }
            #pragma unroll
            for (int mt = 0; mt < 2; mt++)
                #pragma unroll
                for (int nt = 0; nt < 4; nt++) {
                    mma8(c[mt][nt], ah[mt], bh[nt]);
                    mma8(c[mt][nt], al[mt], bh[nt]);
                    mma8(c[mt][nt], ah[mt], bl[nt]);
                }
        }
        __syncthreads();
    }

    // epilogue
    #pragma unroll
    for (int mt = 0; mt < 2; mt++)
        #pragma unroll
        for (int nt = 0; nt < 4; nt++)
            #pragma unroll
            for (int q = 0; q < 4; q++) {
                const int row = m0 + wm + mt * 16 + lr + ((q >= 2) ? 8 : 0);
                const int col = n0 + wn + nt * 8 + lc * 2 + (q & 1);
                float v = c[mt][nt][q] + bias[col];
                if (DST < 3) {
                    // head-major, tf32-round now so attention loads are pre-rounded
                    out[(col >> 6) * (S_LEN * HDIM) + row * HDIM + (col & 63)] =
                        (DST == 2) ? v : v;   // keep fp32; attention rounds at tile load
                } else {
                    out[row * DMODEL + col] = v;
                }
            }
}

// ---------------------------------------------------------------------------
// Causal flash attention with TF32 mma.
// grid = (S/64, NHEADS), 256 threads (8 warps: 4m x 2n).
// smem tiles stride 68 (bank = (4r+c)%32, conflict-free fragment loads).
// ---------------------------------------------------------------------------
#define AST 68
#define ATTN_SMEM_FLOATS (4 * 64 * AST)
#define ATTN_SMEM_BYTES  (ATTN_SMEM_FLOATS * 4)

__global__ void __launch_bounds__(256)
attn_tc()
{
    extern __shared__ float sh[];
    float* Qs = sh;                // [64][68], tf32-rounded
    float* Ks = Qs + 64 * AST;
    float* Vs = Ks + 64 * AST;
    float* Ps = Vs + 64 * AST;
    __shared__ float row_m[64], row_l[64], row_scale[64];

    const int h    = blockIdx.y;
    const int qt   = blockIdx.x;
    const int t    = threadIdx.x;
    const int lane = t & 31;
    const int wid  = t >> 5;
    const int wm   = (wid & 3) * 16;   // 16-row strip
    const int wn   = (wid >> 2) * 32;  // 32-col strip
    const int lr   = lane >> 2;
    const int lc   = lane & 3;

    const float* Qg = g_Q + (h * S_LEN + qt * 64) * HDIM;

    // load Q tile (tf32-rounded into smem)
    #pragma unroll
    for (int i = 0; i < 4; i++) {
        const int idx = t + i * 256;
        const int r = idx >> 4, cg = (idx & 15) * 4;
        float4 v = *(const float4*)(Qg + r * 64 + cg);
        Qs[r * AST + cg + 0] = f2tf_f(v.x); Qs[r * AST + cg + 1] = f2tf_f(v.y);
        Qs[r * AST + cg + 2] = f2tf_f(v.z); Qs[r * AST + cg + 3] = f2tf_f(v.w);
    }
    if (t < 64) { row_m[t] = -1e30f; row_l[t] = 0.0f; }

    float o[4][4];
    #pragma unroll
    for (int nt = 0; nt < 4; nt++)
        #pragma unroll
        for (int q = 0; q < 4; q++) o[nt][q] = 0.0f;

    __syncthreads();

    for (int kt = 0; kt <= qt; kt++) {
        const float* Kg = g_K + (h * S_LEN + kt * 64) * HDIM;
        const float* Vg = g_V + (h * S_LEN + kt * 64) * HDIM;
        #pragma unroll
        for (int i = 0; i < 4; i++) {
            const int idx = t + i * 256;
            const int r = idx >> 4, cg = (idx & 15) * 4;
            float4 kv = *(const float4*)(Kg + r * 64 + cg);
            Ks[r * AST + cg + 0] = f2tf_f(kv.x); Ks[r * AST + cg + 1] = f2tf_f(kv.y);
            Ks[r * AST + cg + 2] = f2tf_f(kv.z); Ks[r * AST + cg + 3] = f2tf_f(kv.w);
            float4 vv = *(const float4*)(Vg + r * 64 + cg);
            Vs[r * AST + cg + 0] = f2tf_f(vv.x); Vs[r * AST + cg + 1] = f2tf_f(vv.y);
            Vs[r * AST + cg + 2] = f2tf_f(vv.z); Vs[r * AST + cg + 3] = f2tf_f(vv.w);
        }
        __syncthreads();

        // S = Q @ K^T : warp computes 16x32
        float s[4][4];
        #pragma unroll
        for (int nt = 0; nt < 4; nt++)
            #pragma unroll
            for (int q = 0; q < 4; q++) s[nt][q] = 0.0f;

        #pragma unroll
        for (int ks = 0; ks < 64; ks += 8) {
            const int kc = ks + lc;
            uint32_t a[4], b[4][2];
            {
                const int r = wm + lr;
                a[0] = __float_as_uint(Qs[r * AST + kc]);
                a[1] = __float_as_uint(Qs[(r + 8) * AST + kc]);
                a[2] = __float_as_uint(Qs[r * AST + kc + 4]);
                a[3] = __float_as_uint(Qs[(r + 8) * AST + kc + 4]);
            }
            #pragma unroll
            for (int nt = 0; nt < 4; nt++) {
                const int n = wn + nt * 8 + lr;
                b[nt][0] = __float_as_uint(Ks[n * AST + kc]);
                b[nt][1] = __float_as_uint(Ks[n * AST + kc + 4]);
            }
            #pragma unroll
            for (int nt = 0; nt < 4; nt++) mma8(s[nt], a, b[nt]);
        }

        // scale + causal mask + store to Ps
        const bool diag = (kt == qt);
        #pragma unroll
        for (int nt = 0; nt < 4; nt++)
            #pragma unroll
            for (int q = 0; q < 4; q++) {
                const int row = wm + lr + ((q >= 2) ? 8 : 0);
                const int col = wn + nt * 8 + lc * 2 + (q & 1);
                float v = s[nt][q] * 0.125f;
                if (diag && col > row) v = -1e30f;
                Ps[row * AST + col] = v;
            }
        __syncthreads();

        // online softmax: 4 threads per row (16 cols each), shfl reduce
        {
            const int r  = t >> 2;
            const int sg = t & 3;
            float* pr = Ps + r * AST + sg * 16;
            const float m_old = row_m[r];
            float m = m_old;
            #pragma unroll
            for (int c2 = 0; c2 < 16; c2++) m = fmaxf(m, pr[c2]);
            m = fmaxf(m, __shfl_xor_sync(0xffffffffu, m, 1));
            m = fmaxf(m, __shfl_xor_sync(0xffffffffu, m, 2));
            const float sc = __expf(m_old - m);
            float sum = 0.0f;
            #pragma unroll
            for (int c2 = 0; c2 < 16; c2++) {
                float p = f2tf_f(__expf(pr[c2] - m));  // tf32-round for PV mma
                pr[c2] = p;
                sum += p;
            }
            sum += __shfl_xor_sync(0xffffffffu, sum, 1);
            sum += __shfl_xor_sync(0xffffffffu, sum, 2);
            if (sg == 0) {
                row_l[r] = row_l[r] * sc + sum;
                row_m[r] = m;
                row_scale[r] = sc;
            }
        }
        __syncthreads();

        // rescale O, then O += P @ V (warp: 16 rows x 32 d-cols)
        #pragma unroll
        for (int q = 0; q < 4; q++) {
            const int row = wm + lr + ((q >= 2) ? 8 : 0);
            const float sc = row_scale[row];
            #pragma unroll
            for (int nt = 0; nt < 4; nt++) o[nt][q] *= sc;
        }
        #pragma unroll
        for (int ks = 0; ks < 64; ks += 8) {
            const int kc = ks + lc;
            uint32_t a[4], b[4][2];
            {
                const int r = wm + lr;
                a[0] = __float_as_uint(Ps[r * AST + kc]);
                a[1] = __float_as_uint(Ps[(r + 8) * AST + kc]);
                a[2] = __float_as_uint(Ps[r * AST + kc + 4]);
                a[3] = __float_as_uint(Ps[(r + 8) * AST + kc + 4]);
            }
            #pragma unroll
            for (int nt = 0; nt < 4; nt++) {
                const int n = wn + nt * 8 + lr;
                b[nt][0] = __float_as_uint(Vs[kc * AST + n]);
                b[nt][1] = __float_as_uint(Vs[(kc + 4) * AST + n]);
            }
            #pragma unroll
            for (int nt = 0; nt < 4; nt++) mma8(o[nt], a, b[nt]);
        }
        __syncthreads();
    }

    // finalize: divide by l, write [S][768]
    #pragma unroll
    for (int q = 0; q < 4; q++) {
        const int row = wm + lr + ((q >= 2) ? 8 : 0);
        const float inv = 1.0f / row_l[row];
        const int srow = qt * 64 + row;
        #pragma unroll
        for (int nt = 0; nt < 4; nt++) {
            const int col = wn + nt * 8 + lc * 2 + (q & 1);
            g_AO[srow * DMODEL + h * HDIM + col] = o[nt][q] * inv;
        }
    }
}

// ---------------------------------------------------------------------------
// Launch
// ---------------------------------------------------------------------------
extern "C" void kernel_launch(void* const* d_in, const int* in_sizes, int n_in,
                              void* d_out, int out_size)
{
    const float* x  = (const float*)d_in[0];
    const float* Wq = (const float*)d_in[1];
    const float* bq = (const float*)d_in[2];
    const float* Wk = (const float*)d_in[3];
    const float* bk = (const float*)d_in[4];
    const float* Wv = (const float*)d_in[5];
    const float* bv = (const float*)d_in[6];
    const float* Wo = (const float*)d_in[7];
    const float* bo = (const float*)d_in[8];
    float* out = (float*)d_out;

    cudaFuncSetAttribute(attn_tc,
                         cudaFuncAttributeMaxDynamicSharedMemorySize,
                         ATTN_SMEM_BYTES);

    dim3 gg(S_LEN / 128, DMODEL / 64);   // 32 x 12
    gemm_tc<0><<<gg, 256>>>(x, Wq, bq, nullptr);
    gemm_tc<1><<<gg, 256>>>(x, Wk, bk, nullptr);
    gemm_tc<2><<<gg, 256>>>(x, Wv, bv, nullptr);

    dim3 ag(S_LEN / 64, NHEADS);         // 64 x 12
    attn_tc<<<ag, 256, ATTN_SMEM_BYTES>>>();

    gemm_tc<3><<<gg, 256>>>(nullptr, Wo, bo, out);
}

// round 3
// speedup vs baseline: 3.6143x; 1.8069x over previous
#include <cuda_runtime.h>
#include <stdint.h>

#define S_LEN   4096
#define DMODEL  768
#define NHEADS  12
#define HDIM    64

// ---------------------------------------------------------------------------
// Scratch
// ---------------------------------------------------------------------------
__device__ float g_Q[NHEADS * S_LEN * HDIM];   // [H][S][64], pre-scaled by 0.125
__device__ float g_K[NHEADS * S_LEN * HDIM];
__device__ float g_V[NHEADS * S_LEN * HDIM];
__device__ float g_AO[S_LEN * DMODEL];

// ---------------------------------------------------------------------------
// Helpers
// ---------------------------------------------------------------------------
__device__ __forceinline__ uint32_t f2tf(float x) {
    uint32_t r;
    asm("cvt.rna.tf32.f32 %0, %1;" : "=r"(r) : "f"(x));
    return r;
}
__device__ __forceinline__ float f2tf_f(float x) { return __uint_as_float(f2tf(x)); }

__device__ __forceinline__ void mma8(float c[4], const uint32_t a[4], const uint32_t b[2]) {
    asm volatile(
        "mma.sync.aligned.m16n8k8.row.col.f32.tf32.tf32.f32 "
        "{%0,%1,%2,%3},{%4,%5,%6,%7},{%8,%9},{%0,%1,%2,%3};"
        : "+f"(c[0]), "+f"(c[1]), "+f"(c[2]), "+f"(c[3])
        : "r"(a[0]), "r"(a[1]), "r"(a[2]), "r"(a[3]), "r"(b[0]), "r"(b[1]));
}

__device__ __forceinline__ void cp_async16(uint32_t dst, const void* src) {
    asm volatile("cp.async.cg.shared.global [%0], [%1], 16;" :: "r"(dst), "l"(src));
}
__device__ __forceinline__ void cp_commit() {
    asm volatile("cp.async.commit_group;" ::: "memory");
}
template <int N>
__device__ __forceinline__ void cp_wait() {
    asm volatile("cp.async.wait_group %0;" :: "n"(N) : "memory");
}
__device__ __forceinline__ uint32_t smem_u32(const void* p) {
    return (uint32_t)__cvta_generic_to_shared(p);
}

// ---------------------------------------------------------------------------
// Projection GEMM, single-pass TF32: C[M,N] = X[M,K] @ W[N,K]^T + bias
// Block tile 128x64, K-step 32, 8 warps (4m x 2n), warp tile 32x32.
// TF32 rounding (rna) applied at smem store.
// DST: 0->g_Q (scaled 0.125), 1->g_K, 2->g_V (head-major), 3->outp ([S][768])
// ---------------------------------------------------------------------------
template <int DST>
__global__ void __launch_bounds__(256)
gemm_tc(const float* __restrict__ Xin, const float* __restrict__ W,
        const float* __restrict__ bias, float* __restrict__ outp)
{
    __shared__ float Xs[128][36];
    __shared__ float Ws[64][36];

    const float* X = (DST == 3) ? (const float*)g_AO : Xin;
    float* out = (DST == 0) ? g_Q : (DST == 1) ? g_K : (DST == 2) ? g_V : outp;

    const int t    = threadIdx.x;
    const int lane = t & 31;
    const int wid  = t >> 5;
    const int m0   = blockIdx.x * 128;
    const int n0   = blockIdx.y * 64;
    const int wm   = (wid & 3) * 32;
    const int wn   = (wid >> 2) * 32;
    const int lr   = lane >> 2;
    const int lc   = lane & 3;

    float c[2][4][4];
    #pragma unroll
    for (int mt = 0; mt < 2; mt++)
        #pragma unroll
        for (int nt = 0; nt < 4; nt++)
            #pragma unroll
            for (int q = 0; q < 4; q++) c[mt][nt][q] = 0.0f;

    for (int k0 = 0; k0 < DMODEL; k0 += 32) {
        #pragma unroll
        for (int i = 0; i < 4; i++) {
            const int idx = t + i * 256;
            const int r = idx >> 3, cg = (idx & 7) * 4;
            float4 v = *(const float4*)(X + (m0 + r) * DMODEL + k0 + cg);
            Xs[r][cg + 0] = f2tf_f(v.x); Xs[r][cg + 1] = f2tf_f(v.y);
            Xs[r][cg + 2] = f2tf_f(v.z); Xs[r][cg + 3] = f2tf_f(v.w);
        }
        #pragma unroll
        for (int i = 0; i < 2; i++) {
            const int idx = t + i * 256;
            const int r = idx >> 3, cg = (idx & 7) * 4;
            float4 v = *(const float4*)(W + (n0 + r) * DMODEL + k0 + cg);
            Ws[r][cg + 0] = f2tf_f(v.x); Ws[r][cg + 1] = f2tf_f(v.y);
            Ws[r][cg + 2] = f2tf_f(v.z); Ws[r][cg + 3] = f2tf_f(v.w);
        }
        __syncthreads();

        #pragma unroll
        for (int ks = 0; ks < 32; ks += 8) {
            const int kc = ks + lc;
            uint32_t a[2][4], b[4][2];
            #pragma unroll
            for (int mt = 0; mt < 2; mt++) {
                const int r = wm + mt * 16 + lr;
                a[mt][0] = __float_as_uint(Xs[r][kc]);
                a[mt][1] = __float_as_uint(Xs[r + 8][kc]);
                a[mt][2] = __float_as_uint(Xs[r][kc + 4]);
                a[mt][3] = __float_as_uint(Xs[r + 8][kc + 4]);
            }
            #pragma unroll
            for (int nt = 0; nt < 4; nt++) {
                const int n = wn + nt * 8 + lr;
                b[nt][0] = __float_as_uint(Ws[n][kc]);
                b[nt][1] = __float_as_uint(Ws[n][kc + 4]);
            }
            #pragma unroll
            for (int mt = 0; mt < 2; mt++)
                #pragma unroll
                for (int nt = 0; nt < 4; nt++)
                    mma8(c[mt][nt], a[mt], b[nt]);
        }
        __syncthreads();
    }

    #pragma unroll
    for (int mt = 0; mt < 2; mt++)
        #pragma unroll
        for (int nt = 0; nt < 4; nt++)
            #pragma unroll
            for (int q = 0; q < 4; q++) {
                const int row = m0 + wm + mt * 16 + lr + ((q >= 2) ? 8 : 0);
                const int col = n0 + wn + nt * 8 + lc * 2 + (q & 1);
                float v = c[mt][nt][q] + bias[col];
                if (DST == 0) v *= 0.125f;   // fold 1/sqrt(HDIM)
                if (DST < 3) {
                    out[(col >> 6) * (S_LEN * HDIM) + row * HDIM + (col & 63)] = v;
                } else {
                    out[row * DMODEL + col] = v;
                }
            }
}

// ---------------------------------------------------------------------------
// Causal flash attention, FA2-style: BQ=128, BK=64, 8 warps (16 rows each).
// Q/S/P/O register-resident; K,V double-buffered via cp.async; softmax via
// quad shuffles; P C-fragment -> A-fragment via shuffles.
// smem stride 68: all fragment access patterns bank-conflict-free.
// ---------------------------------------------------------------------------
#define AST     68
#define TILE_F  (64 * AST)
#define ATTN_SMEM_BYTES (4 * TILE_F * 4)   // K0,V0,K1,V1

__global__ void __launch_bounds__(256)
attn_tc()
{
    extern __shared__ float sh[];   // [K0 | V0 | K1 | V1], each 64*AST floats

    const int h    = blockIdx.y;
    const int qt   = (S_LEN / 128 - 1) - blockIdx.x;   // heavy blocks first
    const int t    = threadIdx.x;
    const int lane = t & 31;
    const int wid  = t >> 5;
    const int wm   = wid * 16;
    const int lr   = lane >> 2;
    const int lc   = lane & 3;

    const float* Qg = g_Q + (h * S_LEN + qt * 128) * HDIM;
    const float* Kg = g_K + h * S_LEN * HDIM;
    const float* Vg = g_V + h * S_LEN * HDIM;

    // ---- stage Q (128x64) into sh rows 0..127 (spans K0+V0), then to regs ----
    #pragma unroll
    for (int i = 0; i < 8; i++) {
        const int idx = t + i * 256;
        const int r = idx >> 4, c4 = (idx & 15) * 4;
        cp_async16(smem_u32(sh + r * AST + c4), Qg + r * 64 + c4);
    }
    cp_commit();
    cp_wait<0>();
    __syncthreads();

    uint32_t q[8][4];
    {
        const float* Qrow = sh + (wm + lr) * AST;
        #pragma unroll
        for (int ks = 0; ks < 8; ks++) {
            const int kc = ks * 8 + lc;
            q[ks][0] = __float_as_uint(Qrow[kc]);
            q[ks][1] = __float_as_uint(Qrow[8 * AST + kc]);
            q[ks][2] = __float_as_uint(Qrow[kc + 4]);
            q[ks][3] = __float_as_uint(Qrow[8 * AST + kc + 4]);
        }
    }
    __syncthreads();   // everyone done reading Q before buf0 is overwritten

    float o[8][4];
    #pragma unroll
    for (int nt = 0; nt < 8; nt++)
        #pragma unroll
        for (int qq = 0; qq < 4; qq++) o[nt][qq] = 0.0f;
    float mA = -1e30f, mB = -1e30f, lA = 0.0f, lB = 0.0f;

    const int ktiles = 2 * qt + 2;

    auto load_tile = [&](int kt2, int b) {
        const float* Kt = Kg + kt2 * 64 * HDIM;
        const float* Vt = Vg + kt2 * 64 * HDIM;
        float* kd = sh + b * 2 * TILE_F;
        float* vd = kd + TILE_F;
        #pragma unroll
        for (int i = 0; i < 4; i++) {
            const int idx = t + i * 256;
            const int r = idx >> 4, c4 = (idx & 15) * 4;
            cp_async16(smem_u32(kd + r * AST + c4), Kt + r * 64 + c4);
            cp_async16(smem_u32(vd + r * AST + c4), Vt + r * 64 + c4);
        }
    };

    load_tile(0, 0);
    cp_commit();

    const int rowA = qt * 128 + wm + lr;
    const int rowB = rowA + 8;

    for (int kt = 0; kt < ktiles; kt++) {
        const int buf = kt & 1;
        if (kt + 1 < ktiles) {
            load_tile(kt + 1, buf ^ 1);
            cp_commit();
            cp_wait<1>();
        } else {
            cp_wait<0>();
        }
        __syncthreads();

        const float* Ks = sh + buf * 2 * TILE_F;
        const float* Vs = Ks + TILE_F;

        // ---- S = Q @ K^T (16x64 per warp, registers) ----
        float s[8][4];
        #pragma unroll
        for (int nt = 0; nt < 8; nt++)
            #pragma unroll
            for (int qq = 0; qq < 4; qq++) s[nt][qq] = 0.0f;

        #pragma unroll
        for (int ks = 0; ks < 8; ks++) {
            const int kc = ks * 8 + lc;
            #pragma unroll
            for (int nt = 0; nt < 8; nt++) {
                const float* kp = Ks + (nt * 8 + lr) * AST + kc;
                uint32_t b[2] = { __float_as_uint(kp[0]), __float_as_uint(kp[4]) };
                mma8(s[nt], q[ks], b);
            }
        }

        // ---- causal mask (only the two diagonal tiles) ----
        if (kt >= 2 * qt) {
            const int col0 = kt * 64;
            #pragma unroll
            for (int nt = 0; nt < 8; nt++) {
                const int c0 = col0 + nt * 8 + 2 * lc;
                if (c0 > rowA)     s[nt][0] = -1e30f;
                if (c0 + 1 > rowA) s[nt][1] = -1e30f;
                if (c0 > rowB)     s[nt][2] = -1e30f;
                if (c0 + 1 > rowB) s[nt][3] = -1e30f;
            }
        }

        // ---- online softmax (rows warp-local: quad shuffles) ----
        float tmA = s[0][0], tmB = s[0][2];
        #pragma unroll
        for (int nt = 0; nt < 8; nt++) {
            tmA = fmaxf(tmA, fmaxf(s[nt][0], s[nt][1]));
            tmB = fmaxf(tmB, fmaxf(s[nt][2], s[nt][3]));
        }
        tmA = fmaxf(tmA, __shfl_xor_sync(0xffffffffu, tmA, 1));
        tmA = fmaxf(tmA, __shfl_xor_sync(0xffffffffu, tmA, 2));
        tmB = fmaxf(tmB, __shfl_xor_sync(0xffffffffu, tmB, 1));
        tmB = fmaxf(tmB, __shfl_xor_sync(0xffffffffu, tmB, 2));

        const float nmA = fmaxf(mA, tmA), nmB = fmaxf(mB, tmB);
        const float scA = __expf(mA - nmA), scB = __expf(mB - nmB);
        mA = nmA; mB = nmB;

        float sumA = 0.0f, sumB = 0.0f;
        #pragma unroll
        for (int nt = 0; nt < 8; nt++) {
            s[nt][0] = __expf(s[nt][0] - mA); sumA += s[nt][0];
            s[nt][1] = __expf(s[nt][1] - mA); sumA += s[nt][1];
            s[nt][2] = __expf(s[nt][2] - mB); sumB += s[nt][2];
            s[nt][3] = __expf(s[nt][3] - mB); sumB += s[nt][3];
        }
        sumA += __shfl_xor_sync(0xffffffffu, sumA, 1);
        sumA += __shfl_xor_sync(0xffffffffu, sumA, 2);
        sumB += __shfl_xor_sync(0xffffffffu, sumB, 1);
        sumB += __shfl_xor_sync(0xffffffffu, sumB, 2);
        lA = lA * scA + sumA;
        lB = lB * scB + sumB;

        #pragma unroll
        for (int nt = 0; nt < 8; nt++) {
            o[nt][0] *= scA; o[nt][1] *= scA;
            o[nt][2] *= scB; o[nt][3] *= scB;
        }

        // ---- O += P @ V ; P C-frag -> A-frag via quad shuffles ----
        const int src_lo = (lane & ~3) | (lc >> 1);
        const int src_hi = src_lo + 2;
        const bool odd = (lc & 1);
        #pragma unroll
        for (int ks2 = 0; ks2 < 8; ks2++) {
            const float p0 = s[ks2][0], p1 = s[ks2][1];
            const float p2 = s[ks2][2], p3 = s[ks2][3];
            const float v0l = __shfl_sync(0xffffffffu, p0, src_lo);
            const float v1l = __shfl_sync(0xffffffffu, p1, src_lo);
            const float v0h = __shfl_sync(0xffffffffu, p0, src_hi);
            const float v1h = __shfl_sync(0xffffffffu, p1, src_hi);
            const float w0l = __shfl_sync(0xffffffffu, p2, src_lo);
            const float w1l = __shfl_sync(0xffffffffu, p3, src_lo);
            const float w0h = __shfl_sync(0xffffffffu, p2, src_hi);
            const float w1h = __shfl_sync(0xffffffffu, p3, src_hi);
            uint32_t a[4];
            a[0] = __float_as_uint(odd ? v1l : v0l);
            a[1] = __float_as_uint(odd ? w1l : w0l);
            a[2] = __float_as_uint(odd ? v1h : v0h);
            a[3] = __float_as_uint(odd ? w1h : w0h);

            const float* vp = Vs + (ks2 * 8 + lc) * AST;
            #pragma unroll
            for (int nt = 0; nt < 8; nt++) {
                uint32_t b[2] = { __float_as_uint(vp[nt * 8 + lr]),
                                  __float_as_uint(vp[4 * AST + nt * 8 + lr]) };
                mma8(o[nt], a, b);
            }
        }
        __syncthreads();   // all warps done reading buf before it is refilled
    }

    // ---- epilogue ----
    const float invA = 1.0f / lA, invB = 1.0f / lB;
    #pragma unroll
    for (int nt = 0; nt < 8; nt++) {
        const int col = h * HDIM + nt * 8 + 2 * lc;
        float2 va = { o[nt][0] * invA, o[nt][1] * invA };
        float2 vb = { o[nt][2] * invB, o[nt][3] * invB };
        *(float2*)&g_AO[rowA * DMODEL + col] = va;
        *(float2*)&g_AO[rowB * DMODEL + col] = vb;
    }
}

// ---------------------------------------------------------------------------
// Launch
// ---------------------------------------------------------------------------
extern "C" void kernel_launch(void* const* d_in, const int* in_sizes, int n_in,
                              void* d_out, int out_size)
{
    const float* x  = (const float*)d_in[0];
    const float* Wq = (const float*)d_in[1];
    const float* bq = (const float*)d_in[2];
    const float* Wk = (const float*)d_in[3];
    const float* bk = (const float*)d_in[4];
    const float* Wv = (const float*)d_in[5];
    const float* bv = (const float*)d_in[6];
    const float* Wo = (const float*)d_in[7];
    const float* bo = (const float*)d_in[8];
    float* out = (float*)d_out;

    cudaFuncSetAttribute(attn_tc,
                         cudaFuncAttributeMaxDynamicSharedMemorySize,
                         ATTN_SMEM_BYTES);

    dim3 gg(S_LEN / 128, DMODEL / 64);   // 32 x 12
    gemm_tc<0><<<gg, 256>>>(x, Wq, bq, nullptr);
    gemm_tc<1><<<gg, 256>>>(x, Wk, bk, nullptr);
    gemm_tc<2><<<gg, 256>>>(x, Wv, bv, nullptr);

    dim3 ag(S_LEN / 128, NHEADS);        // 32 x 12
    attn_tc<<<ag, 256, ATTN_SMEM_BYTES>>>();

    gemm_tc<3><<<gg, 256>>>(nullptr, Wo, bo, out);
}

// round 5
// speedup vs baseline: 3.9523x; 1.0935x over previous
#include <cuda_runtime.h>
#include <stdint.h>

#define S_LEN   4096
#define DMODEL  768
#define NHEADS  12
#define HDIM    64
#define WN      (DMODEL * DMODEL)

// ---------------------------------------------------------------------------
// Scratch (device globals)
// ---------------------------------------------------------------------------
__device__ float g_Q[NHEADS * S_LEN * HDIM];   // [H][S][64], pre-scaled 0.125
__device__ float g_K[NHEADS * S_LEN * HDIM];
__device__ float g_V[NHEADS * S_LEN * HDIM];
__device__ float g_AO[S_LEN * DMODEL];         // tf32-rounded attention output
__device__ float g_Xtf[S_LEN * DMODEL];        // tf32-rounded input
__device__ float g_Wt[4 * WN];                 // tf32-rounded Wq,Wk,Wv,Wo

// ---------------------------------------------------------------------------
// Helpers
// ---------------------------------------------------------------------------
__device__ __forceinline__ uint32_t smem_u32(const void* p) {
    return (uint32_t)__cvta_generic_to_shared(p);
}
__device__ __forceinline__ uint32_t f2tf(float x) {
    uint32_t r;
    asm("cvt.rna.tf32.f32 %0, %1;" : "=r"(r) : "f"(x));
    return r;
}
__device__ __forceinline__ float f2tf_f(float x) { return __uint_as_float(f2tf(x)); }

__device__ __forceinline__ void mma8(float c[4], const uint32_t a[4], const uint32_t b[2]) {
    asm volatile(
        "mma.sync.aligned.m16n8k8.row.col.f32.tf32.tf32.f32 "
        "{%0,%1,%2,%3},{%4,%5,%6,%7},{%8,%9},{%0,%1,%2,%3};"
        : "+f"(c[0]), "+f"(c[1]), "+f"(c[2]), "+f"(c[3])
        : "r"(a[0]), "r"(a[1]), "r"(a[2]), "r"(a[3]), "r"(b[0]), "r"(b[1]));
}
__device__ __forceinline__ void cp_async16(uint32_t dst, const void* src) {
    asm volatile("cp.async.cg.shared.global [%0], [%1], 16;" :: "r"(dst), "l"(src));
}
__device__ __forceinline__ void cp_commit() {
    asm volatile("cp.async.commit_group;" ::: "memory");
}
template <int N>
__device__ __forceinline__ void cp_wait() {
    asm volatile("cp.async.wait_group %0;" :: "n"(N) : "memory");
}

// ---------------------------------------------------------------------------
// Prep: tf32-round x -> g_Xtf and Wq/Wk/Wv/Wo -> g_Wt (one float4/thread)
// ---------------------------------------------------------------------------
#define XN4 (S_LEN * DMODEL / 4)
#define WN4 (WN / 4)
#define PREP_TOTAL (XN4 + 4 * WN4)

__global__ void __launch_bounds__(256)
prep_round(const float* __restrict__ x,  const float* __restrict__ Wq,
           const float* __restrict__ Wk, const float* __restrict__ Wv,
           const float* __restrict__ Wo)
{
    const int i = blockIdx.x * 256 + threadIdx.x;
    if (i >= PREP_TOTAL) return;
    const float* src;
    float* dst;
    int off;
    if (i < XN4) {
        src = x; dst = g_Xtf; off = i;
    } else {
        const int j = i - XN4;
        const int w = j / WN4;
        off = j - w * WN4;
        src = (w == 0) ? Wq : (w == 1) ? Wk : (w == 2) ? Wv : Wo;
        dst = g_Wt + w * WN;
    }
    float4 v = ((const float4*)src)[off];
    v.x = f2tf_f(v.x); v.y = f2tf_f(v.y); v.z = f2tf_f(v.z); v.w = f2tf_f(v.w);
    ((float4*)dst)[off] = v;
}

// ---------------------------------------------------------------------------
// Projection GEMM (tf32, inputs pre-rounded -> no cvt in mainloop).
// C[M,N] = X[M,K] @ W[N,K]^T + bias.  CTA tile 128x128, K-step 32,
// cp.async double-buffered.  8 warps as 2m x 4n, warp tile 64x32.
// OPROJ=0: fused QKV (blockIdx.z selects W/bias/out, head-major store,
//          z==0 scaled by 0.125).  OPROJ=1: O projection -> outO [S][768].
// ---------------------------------------------------------------------------
#define PB 36
#define PJ_TILE (128 * PB)                 // floats per (buf, matrix)
#define PJ_SMEM (4 * PJ_TILE * 4)          // 2 bufs x (X + W) = 73728 B

template <int OPROJ>
__global__ void __launch_bounds__(256)
proj_tf(const float* __restrict__ b0, const float* __restrict__ b1,
        const float* __restrict__ b2, float* __restrict__ outO)
{
    extern __shared__ float sh[];
    float* Xs = sh;                        // [2][128][PB]
    float* Ws = sh + 2 * PJ_TILE;          // [2][128][PB]

    const int t    = threadIdx.x;
    const int lane = t & 31;
    const int wid  = t >> 5;
    const int m0   = blockIdx.x * 128;
    const int n0   = blockIdx.y * 128;
    const int z    = OPROJ ? 3 : blockIdx.z;

    const float* X    = OPROJ ? g_AO : g_Xtf;
    const float* W    = g_Wt + z * WN;
    const float* bias = OPROJ ? b0 : (z == 0 ? b0 : (z == 1 ? b1 : b2));
    float* outH = (z == 0) ? g_Q : (z == 1) ? g_K : g_V;

    const int wm = (wid & 1) * 64;
    const int wn = (wid >> 1) * 32;
    const int lr = lane >> 2;
    const int lc = lane & 3;

    float c[4][4][4];
    #pragma unroll
    for (int mt = 0; mt < 4; mt++)
        #pragma unroll
        for (int nt = 0; nt < 4; nt++)
            #pragma unroll
            for (int q = 0; q < 4; q++) c[mt][nt][q] = 0.0f;

    auto load = [&](int kt, int buf) {
        const int k0 = kt * 32;
        #pragma unroll
        for (int i = 0; i < 4; i++) {
            const int e = t + i * 256;
            const int r = e >> 3, c4 = (e & 7) * 4;
            cp_async16(smem_u32(Xs + buf * PJ_TILE + r * PB + c4),
                       X + (m0 + r) * DMODEL + k0 + c4);
            cp_async16(smem_u32(Ws + buf * PJ_TILE + r * PB + c4),
                       W + (n0 + r) * DMODEL + k0 + c4);
        }
    };

    load(0, 0);
    cp_commit();

    for (int kt = 0; kt < DMODEL / 32; kt++) {
        const int buf = kt & 1;
        if (kt + 1 < DMODEL / 32) {
            load(kt + 1, buf ^ 1);
            cp_commit();
            cp_wait<1>();
        } else {
            cp_wait<0>();
        }
        __syncthreads();

        const float* Xb = Xs + buf * PJ_TILE;
        const float* Wb = Ws + buf * PJ_TILE;

        #pragma unroll
        for (int ks = 0; ks < 32; ks += 8) {
            const int kc = ks + lc;
            uint32_t a[4][4], b[4][2];
            #pragma unroll
            for (int mt = 0; mt < 4; mt++) {
                const float* xp = Xb + (wm + mt * 16 + lr) * PB + kc;
                a[mt][0] = __float_as_uint(xp[0]);
                a[mt][1] = __float_as_uint(xp[8 * PB]);
                a[mt][2] = __float_as_uint(xp[4]);
                a[mt][3] = __float_as_uint(xp[8 * PB + 4]);
            }
            #pragma unroll
            for (int nt = 0; nt < 4; nt++) {
                const float* wp = Wb + (wn + nt * 8 + lr) * PB + kc;
                b[nt][0] = __float_as_uint(wp[0]);
                b[nt][1] = __float_as_uint(wp[4]);
            }
            #pragma unroll
            for (int mt = 0; mt < 4; mt++)
                #pragma unroll
                for (int nt = 0; nt < 4; nt++)
                    mma8(c[mt][nt], a[mt], b[nt]);
        }
        __syncthreads();
    }

    // epilogue
    #pragma unroll
    for (int mt = 0; mt < 4; mt++) {
        #pragma unroll
        for (int nt = 0; nt < 4; nt++) {
            const int col = n0 + wn + nt * 8 + lc * 2;
            const float bx = bias[col], by = bias[col + 1];
            #pragma unroll
            for (int half = 0; half < 2; half++) {
                const int row = m0 + wm + mt * 16 + lr + half * 8;
                float2 v = { c[mt][nt][half * 2 + 0] + bx,
                             c[mt][nt][half * 2 + 1] + by };
                if (!OPROJ) {
                    if (z == 0) { v.x *= 0.125f; v.y *= 0.125f; }
                    // head-major: [head][seq][hd]; col..col+1 within one head
                    *(float2*)&outH[(col >> 6) * (S_LEN * HDIM) + row * HDIM + (col & 63)] = v;
                } else {
                    *(float2*)&outO[row * DMODEL + col] = v;
                }
            }
        }
    }
}

// ---------------------------------------------------------------------------
// Causal flash attention (identical to R3 except tf32-rounded g_AO writes).
// TF32 mma, BQ=128, BK=64, 8 warps x 16 rows, register-resident Q/S/P/O,
// cp.async double buffering.  smem stride 68 -> conflict-free fragments.
// ---------------------------------------------------------------------------
#define AST     68
#define TILE_F  (64 * AST)
#define ATTN_SMEM_BYTES (4 * TILE_F * 4)

__global__ void __launch_bounds__(256)
attn_tc()
{
    extern __shared__ float sh[];

    const int h    = blockIdx.y;
    const int qt   = (S_LEN / 128 - 1) - blockIdx.x;
    const int t    = threadIdx.x;
    const int lane = t & 31;
    const int wid  = t >> 5;
    const int wm   = wid * 16;
    const int lr   = lane >> 2;
    const int lc   = lane & 3;

    const float* Qg = g_Q + (h * S_LEN + qt * 128) * HDIM;
    const float* Kg = g_K + h * S_LEN * HDIM;
    const float* Vg = g_V + h * S_LEN * HDIM;

    #pragma unroll
    for (int i = 0; i < 8; i++) {
        const int idx = t + i * 256;
        const int r = idx >> 4, c4 = (idx & 15) * 4;
        cp_async16(smem_u32(sh + r * AST + c4), Qg + r * 64 + c4);
    }
    cp_commit();
    cp_wait<0>();
    __syncthreads();

    uint32_t q[8][4];
    {
        const float* Qrow = sh + (wm + lr) * AST;
        #pragma unroll
        for (int ks = 0; ks < 8; ks++) {
            const int kc = ks * 8 + lc;
            q[ks][0] = __float_as_uint(Qrow[kc]);
            q[ks][1] = __float_as_uint(Qrow[8 * AST + kc]);
            q[ks][2] = __float_as_uint(Qrow[kc + 4]);
            q[ks][3] = __float_as_uint(Qrow[8 * AST + kc + 4]);
        }
    }
    __syncthreads();

    float o[8][4];
    #pragma unroll
    for (int nt = 0; nt < 8; nt++)
        #pragma unroll
        for (int qq = 0; qq < 4; qq++) o[nt][qq] = 0.0f;
    float mA = -1e30f, mB = -1e30f, lA = 0.0f, lB = 0.0f;

    const int ktiles = 2 * qt + 2;

    auto load_tile = [&](int kt2, int b) {
        const float* Kt = Kg + kt2 * 64 * HDIM;
        const float* Vt = Vg + kt2 * 64 * HDIM;
        float* kd = sh + b * 2 * TILE_F;
        float* vd = kd + TILE_F;
        #pragma unroll
        for (int i = 0; i < 4; i++) {
            const int idx = t + i * 256;
            const int r = idx >> 4, c4 = (idx & 15) * 4;
            cp_async16(smem_u32(kd + r * AST + c4), Kt + r * 64 + c4);
            cp_async16(smem_u32(vd + r * AST + c4), Vt + r * 64 + c4);
        }
    };

    load_tile(0, 0);
    cp_commit();

    const int rowA = qt * 128 + wm + lr;
    const int rowB = rowA + 8;

    for (int kt = 0; kt < ktiles; kt++) {
        const int buf = kt & 1;
        if (kt + 1 < ktiles) {
            load_tile(kt + 1, buf ^ 1);
            cp_commit();
            cp_wait<1>();
        } else {
            cp_wait<0>();
        }
        __syncthreads();

        const float* Ks = sh + buf * 2 * TILE_F;
        const float* Vs = Ks + TILE_F;

        float s[8][4];
        #pragma unroll
        for (int nt = 0; nt < 8; nt++)
            #pragma unroll
            for (int qq = 0; qq < 4; qq++) s[nt][qq] = 0.0f;

        #pragma unroll
        for (int ks = 0; ks < 8; ks++) {
            const int kc = ks * 8 + lc;
            #pragma unroll
            for (int nt = 0; nt < 8; nt++) {
                const float* kp = Ks + (nt * 8 + lr) * AST + kc;
                uint32_t b[2] = { __float_as_uint(kp[0]), __float_as_uint(kp[4]) };
                mma8(s[nt], q[ks], b);
            }
        }

        if (kt >= 2 * qt) {
            const int col0 = kt * 64;
            #pragma unroll
            for (int nt = 0; nt < 8; nt++) {
                const int c0 = col0 + nt * 8 + 2 * lc;
                if (c0 > rowA)     s[nt][0] = -1e30f;
                if (c0 + 1 > rowA) s[nt][1] = -1e30f;
                if (c0 > rowB)     s[nt][2] = -1e30f;
                if (c0 + 1 > rowB) s[nt][3] = -1e30f;
            }
        }

        float tmA = s[0][0], tmB = s[0][2];
        #pragma unroll
        for (int nt = 0; nt < 8; nt++) {
            tmA = fmaxf(tmA, fmaxf(s[nt][0], s[nt][1]));
            tmB = fmaxf(tmB, fmaxf(s[nt][2], s[nt][3]));
        }
        tmA = fmaxf(tmA, __shfl_xor_sync(0xffffffffu, tmA, 1));
        tmA = fmaxf(tmA, __shfl_xor_sync(0xffffffffu, tmA, 2));
        tmB = fmaxf(tmB, __shfl_xor_sync(0xffffffffu, tmB, 1));
        tmB = fmaxf(tmB, __shfl_xor_sync(0xffffffffu, tmB, 2));

        const float nmA = fmaxf(mA, tmA), nmB = fmaxf(mB, tmB);
        const float scA = __expf(mA - nmA), scB = __expf(mB - nmB);
        mA = nmA; mB = nmB;

        float sumA = 0.0f, sumB = 0.0f;
        #pragma unroll
        for (int nt = 0; nt < 8; nt++) {
            s[nt][0] = __expf(s[nt][0] - mA); sumA += s[nt][0];
            s[nt][1] = __expf(s[nt][1] - mA); sumA += s[nt][1];
            s[nt][2] = __expf(s[nt][2] - mB); sumB += s[nt][2];
            s[nt][3] = __expf(s[nt][3] - mB); sumB += s[nt][3];
        }
        sumA += __shfl_xor_sync(0xffffffffu, sumA, 1);
        sumA += __shfl_xor_sync(0xffffffffu, sumA, 2);
        sumB += __shfl_xor_sync(0xffffffffu, sumB, 1);
        sumB += __shfl_xor_sync(0xffffffffu, sumB, 2);
        lA = lA * scA + sumA;
        lB = lB * scB + sumB;

        #pragma unroll
        for (int nt = 0; nt < 8; nt++) {
            o[nt][0] *= scA; o[nt][1] *= scA;
            o[nt][2] *= scB; o[nt][3] *= scB;
        }

        const int src_lo = (lane & ~3) | (lc >> 1);
        const int src_hi = src_lo + 2;
        const bool odd = (lc & 1);
        #pragma unroll
        for (int ks2 = 0; ks2 < 8; ks2++) {
            const float p0 = s[ks2][0], p1 = s[ks2][1];
            const float p2 = s[ks2][2], p3 = s[ks2][3];
            const float v0l = __shfl_sync(0xffffffffu, p0, src_lo);
            const float v1l = __shfl_sync(0xffffffffu, p1, src_lo);
            const float v0h = __shfl_sync(0xffffffffu, p0, src_hi);
            const float v1h = __shfl_sync(0xffffffffu, p1, src_hi);
            const float w0l = __shfl_sync(0xffffffffu, p2, src_lo);
            const float w1l = __shfl_sync(0xffffffffu, p3, src_lo);
            const float w0h = __shfl_sync(0xffffffffu, p2, src_hi);
            const float w1h = __shfl_sync(0xffffffffu, p3, src_hi);
            uint32_t a[4];
            a[0] = __float_as_uint(odd ? v1l : v0l);
            a[1] = __float_as_uint(odd ? w1l : w0l);
            a[2] = __float_as_uint(odd ? v1h : v0h);
            a[3] = __float_as_uint(odd ? w1h : w0h);

            const float* vp = Vs + (ks2 * 8 + lc) * AST;
            #pragma unroll
            for (int nt = 0; nt < 8; nt++) {
                uint32_t b[2] = { __float_as_uint(vp[nt * 8 + lr]),
                                  __float_as_uint(vp[4 * AST + nt * 8 + lr]) };
                mma8(o[nt], a, b);
            }
        }
        __syncthreads();
    }

    // epilogue: tf32-round so the O projection needs no conversion
    const float invA = 1.0f / lA, invB = 1.0f / lB;
    #pragma unroll
    for (int nt = 0; nt < 8; nt++) {
        const int col = h * HDIM + nt * 8 + 2 * lc;
        float2 va = { f2tf_f(o[nt][0] * invA), f2tf_f(o[nt][1] * invA) };
        float2 vb = { f2tf_f(o[nt][2] * invB), f2tf_f(o[nt][3] * invB) };
        *(float2*)&g_AO[rowA * DMODEL + col] = va;
        *(float2*)&g_AO[rowB * DMODEL + col] = vb;
    }
}

// ---------------------------------------------------------------------------
// Launch
// ---------------------------------------------------------------------------
extern "C" void kernel_launch(void* const* d_in, const int* in_sizes, int n_in,
                              void* d_out, int out_size)
{
    const float* x  = (const float*)d_in[0];
    const float* Wq = (const float*)d_in[1];
    const float* bq = (const float*)d_in[2];
    const float* Wk = (const float*)d_in[3];
    const float* bk = (const float*)d_in[4];
    const float* Wv = (const float*)d_in[5];
    const float* bv = (const float*)d_in[6];
    const float* Wo = (const float*)d_in[7];
    const float* bo = (const float*)d_in[8];
    float* out = (float*)d_out;

    cudaFuncSetAttribute(proj_tf<0>, cudaFuncAttributeMaxDynamicSharedMemorySize, PJ_SMEM);
    cudaFuncSetAttribute(proj_tf<1>, cudaFuncAttributeMaxDynamicSharedMemorySize, PJ_SMEM);
    cudaFuncSetAttribute(attn_tc,    cudaFuncAttributeMaxDynamicSharedMemorySize, ATTN_SMEM_BYTES);

    prep_round<<<(PREP_TOTAL + 255) / 256, 256>>>(x, Wq, Wk, Wv, Wo);

    dim3 gq(S_LEN / 128, DMODEL / 128, 3);   // 32 x 6 x 3
    proj_tf<0><<<gq, 256, PJ_SMEM>>>(bq, bk, bv, nullptr);

    dim3 ag(S_LEN / 128, NHEADS);            // 32 x 12
    attn_tc<<<ag, 256, ATTN_SMEM_BYTES>>>();

    dim3 go(S_LEN / 128, DMODEL / 128);      // 32 x 6
    proj_tf<1><<<go, 256, PJ_SMEM>>>(bo, nullptr, nullptr, out);
}

// round 6
// speedup vs baseline: 4.3843x; 1.1093x over previous
#include <cuda_runtime.h>
#include <stdint.h>

#define S_LEN   4096
#define DMODEL  768
#define NHEADS  12
#define HDIM    64
#define WN      (DMODEL * DMODEL)

// ---------------------------------------------------------------------------
// Scratch (device globals)
// ---------------------------------------------------------------------------
__device__ float g_Q[NHEADS * S_LEN * HDIM];   // [H][S][64], pre-scaled 0.125
__device__ float g_K[NHEADS * S_LEN * HDIM];
__device__ float g_V[NHEADS * S_LEN * HDIM];
__device__ float g_AO[S_LEN * DMODEL];         // tf32-rounded attention output
__device__ float g_Xtf[S_LEN * DMODEL];        // tf32-rounded input
__device__ float g_Wt[4 * WN];                 // tf32-rounded Wq,Wk,Wv,Wo

// ---------------------------------------------------------------------------
// Helpers
// ---------------------------------------------------------------------------
__device__ __forceinline__ uint32_t smem_u32(const void* p) {
    return (uint32_t)__cvta_generic_to_shared(p);
}
__device__ __forceinline__ uint32_t f2tf(float x) {
    uint32_t r;
    asm("cvt.rna.tf32.f32 %0, %1;" : "=r"(r) : "f"(x));
    return r;
}
__device__ __forceinline__ float f2tf_f(float x) { return __uint_as_float(f2tf(x)); }

__device__ __forceinline__ void mma8(float c[4], const uint32_t a[4], const uint32_t b[2]) {
    asm volatile(
        "mma.sync.aligned.m16n8k8.row.col.f32.tf32.tf32.f32 "
        "{%0,%1,%2,%3},{%4,%5,%6,%7},{%8,%9},{%0,%1,%2,%3};"
        : "+f"(c[0]), "+f"(c[1]), "+f"(c[2]), "+f"(c[3])
        : "r"(a[0]), "r"(a[1]), "r"(a[2]), "r"(a[3]), "r"(b[0]), "r"(b[1]));
}
__device__ __forceinline__ void cp_async16(uint32_t dst, const void* src) {
    asm volatile("cp.async.cg.shared.global [%0], [%1], 16;" :: "r"(dst), "l"(src));
}
__device__ __forceinline__ void cp_commit() {
    asm volatile("cp.async.commit_group;" ::: "memory");
}
template <int N>
__device__ __forceinline__ void cp_wait() {
    asm volatile("cp.async.wait_group %0;" :: "n"(N) : "memory");
}

// ---------------------------------------------------------------------------
// Prep: tf32-round x -> g_Xtf and Wq/Wk/Wv/Wo -> g_Wt
// ---------------------------------------------------------------------------
#define XN4 (S_LEN * DMODEL / 4)
#define WN4 (WN / 4)
#define PREP_TOTAL (XN4 + 4 * WN4)

__global__ void __launch_bounds__(256)
prep_round(const float* __restrict__ x,  const float* __restrict__ Wq,
           const float* __restrict__ Wk, const float* __restrict__ Wv,
           const float* __restrict__ Wo)
{
    const int i = blockIdx.x * 256 + threadIdx.x;
    if (i >= PREP_TOTAL) return;
    const float* src;
    float* dst;
    int off;
    if (i < XN4) {
        src = x; dst = g_Xtf; off = i;
    } else {
        const int j = i - XN4;
        const int w = j / WN4;
        off = j - w * WN4;
        src = (w == 0) ? Wq : (w == 1) ? Wk : (w == 2) ? Wv : Wo;
        dst = g_Wt + w * WN;
    }
    float4 v = ((const float4*)src)[off];
    v.x = f2tf_f(v.x); v.y = f2tf_f(v.y); v.z = f2tf_f(v.z); v.w = f2tf_f(v.w);
    ((float4*)dst)[off] = v;
}

// ---------------------------------------------------------------------------
// Projection GEMM (tf32, pre-rounded inputs).  C = X @ W^T + bias.
// CTA tile BM x 128, K-step 32, cp.async double-buffered, 256 threads,
// 8 warps (2m x 4n), warp tile (BM/2) x 32.
// OPROJ=0: fused QKV (blockIdx.z selects, head-major store, z==0 scaled).
// OPROJ=1: O projection -> outO [S][768].
// ---------------------------------------------------------------------------
#define PB 36

template <int OPROJ, int BM>
__global__ void __launch_bounds__(256)
proj_tf(const float* __restrict__ b0, const float* __restrict__ b1,
        const float* __restrict__ b2, float* __restrict__ outO)
{
    constexpr int MT     = BM / 32;        // m-frags per warp
    constexpr int XTILE  = BM * PB;
    constexpr int WTILE  = 128 * PB;

    extern __shared__ float sh[];
    float* Xs = sh;                        // [2][BM][PB]
    float* Ws = sh + 2 * XTILE;            // [2][128][PB]

    const int t    = threadIdx.x;
    const int lane = t & 31;
    const int wid  = t >> 5;
    const int m0   = blockIdx.x * BM;
    const int n0   = blockIdx.y * 128;
    const int z    = OPROJ ? 3 : blockIdx.z;

    const float* X    = OPROJ ? g_AO : g_Xtf;
    const float* W    = g_Wt + z * WN;
    const float* bias = OPROJ ? b0 : (z == 0 ? b0 : (z == 1 ? b1 : b2));
    float* outH = (z == 0) ? g_Q : (z == 1) ? g_K : g_V;

    const int wm = (wid & 1) * (BM / 2);
    const int wn = (wid >> 1) * 32;
    const int lr = lane >> 2;
    const int lc = lane & 3;

    float c[MT][4][4];
    #pragma unroll
    for (int mt = 0; mt < MT; mt++)
        #pragma unroll
        for (int nt = 0; nt < 4; nt++)
            #pragma unroll
            for (int q = 0; q < 4; q++) c[mt][nt][q] = 0.0f;

    auto load = [&](int kt, int buf) {
        const int k0 = kt * 32;
        #pragma unroll
        for (int i = 0; i < BM / 32; i++) {
            const int e = t + i * 256;
            const int r = e >> 3, c4 = (e & 7) * 4;
            cp_async16(smem_u32(Xs + buf * XTILE + r * PB + c4),
                       X + (m0 + r) * DMODEL + k0 + c4);
        }
        #pragma unroll
        for (int i = 0; i < 4; i++) {
            const int e = t + i * 256;
            const int r = e >> 3, c4 = (e & 7) * 4;
            cp_async16(smem_u32(Ws + buf * WTILE + r * PB + c4),
                       W + (n0 + r) * DMODEL + k0 + c4);
        }
    };

    load(0, 0);
    cp_commit();

    for (int kt = 0; kt < DMODEL / 32; kt++) {
        const int buf = kt & 1;
        if (kt + 1 < DMODEL / 32) {
            load(kt + 1, buf ^ 1);
            cp_commit();
            cp_wait<1>();
        } else {
            cp_wait<0>();
        }
        __syncthreads();

        const float* Xb = Xs + buf * XTILE;
        const float* Wb = Ws + buf * WTILE;

        #pragma unroll
        for (int ks = 0; ks < 32; ks += 8) {
            const int kc = ks + lc;
            uint32_t a[MT][4], b[4][2];
            #pragma unroll
            for (int mt = 0; mt < MT; mt++) {
                const float* xp = Xb + (wm + mt * 16 + lr) * PB + kc;
                a[mt][0] = __float_as_uint(xp[0]);
                a[mt][1] = __float_as_uint(xp[8 * PB]);
                a[mt][2] = __float_as_uint(xp[4]);
                a[mt][3] = __float_as_uint(xp[8 * PB + 4]);
            }
            #pragma unroll
            for (int nt = 0; nt < 4; nt++) {
                const float* wp = Wb + (wn + nt * 8 + lr) * PB + kc;
                b[nt][0] = __float_as_uint(wp[0]);
                b[nt][1] = __float_as_uint(wp[4]);
            }
            #pragma unroll
            for (int mt = 0; mt < MT; mt++)
                #pragma unroll
                for (int nt = 0; nt < 4; nt++)
                    mma8(c[mt][nt], a[mt], b[nt]);
        }
        __syncthreads();
    }

    // epilogue
    #pragma unroll
    for (int mt = 0; mt < MT; mt++) {
        #pragma unroll
        for (int nt = 0; nt < 4; nt++) {
            const int col = n0 + wn + nt * 8 + lc * 2;
            const float bx = bias[col], by = bias[col + 1];
            #pragma unroll
            for (int half = 0; half < 2; half++) {
                const int row = m0 + wm + mt * 16 + lr + half * 8;
                float2 v = { c[mt][nt][half * 2 + 0] + bx,
                             c[mt][nt][half * 2 + 1] + by };
                if (!OPROJ) {
                    if (z == 0) { v.x *= 0.125f; v.y *= 0.125f; }
                    *(float2*)&outH[(col >> 6) * (S_LEN * HDIM) + row * HDIM + (col & 63)] = v;
                } else {
                    *(float2*)&outO[row * DMODEL + col] = v;
                }
            }
        }
    }
}

// ---------------------------------------------------------------------------
// Causal flash attention.  BQ=64, BK=64, 128 threads (4 warps x 16 rows),
// register-resident Q/S/P/O, cp.async double buffering, 3 CTAs/SM.
// Per-row math identical to R5 (same BK=64 tile sequence).
// ---------------------------------------------------------------------------
#define AST     68
#define TILE_F  (64 * AST)
#define ATTN_SMEM_BYTES (4 * TILE_F * 4)   // 69632: K0,V0,K1,V1

__global__ void __launch_bounds__(128, 3)
attn_tc()
{
    extern __shared__ float sh[];

    const int h    = blockIdx.y;
    const int qt   = (S_LEN / 64 - 1) - blockIdx.x;   // heavy blocks first
    const int t    = threadIdx.x;
    const int lane = t & 31;
    const int wid  = t >> 5;
    const int wm   = wid * 16;
    const int lr   = lane >> 2;
    const int lc   = lane & 3;

    const float* Qg = g_Q + (h * S_LEN + qt * 64) * HDIM;
    const float* Kg = g_K + h * S_LEN * HDIM;
    const float* Vg = g_V + h * S_LEN * HDIM;

    // ---- stage Q (64x64) into tile0 region, then to regs ----
    #pragma unroll
    for (int i = 0; i < 8; i++) {
        const int idx = t + i * 128;
        const int r = idx >> 4, c4 = (idx & 15) * 4;
        cp_async16(smem_u32(sh + r * AST + c4), Qg + r * 64 + c4);
    }
    cp_commit();
    cp_wait<0>();
    __syncthreads();

    uint32_t q[8][4];
    {
        const float* Qrow = sh + (wm + lr) * AST;
        #pragma unroll
        for (int ks = 0; ks < 8; ks++) {
            const int kc = ks * 8 + lc;
            q[ks][0] = __float_as_uint(Qrow[kc]);
            q[ks][1] = __float_as_uint(Qrow[8 * AST + kc]);
            q[ks][2] = __float_as_uint(Qrow[kc + 4]);
            q[ks][3] = __float_as_uint(Qrow[8 * AST + kc + 4]);
        }
    }
    __syncthreads();   // all q reads done before buf0 refill

    float o[8][4];
    #pragma unroll
    for (int nt = 0; nt < 8; nt++)
        #pragma unroll
        for (int qq = 0; qq < 4; qq++) o[nt][qq] = 0.0f;
    float mA = -1e30f, mB = -1e30f, lA = 0.0f, lB = 0.0f;

    const int ktiles = qt + 1;

    auto load_tile = [&](int kt2, int b) {
        const float* Kt = Kg + kt2 * 64 * HDIM;
        const float* Vt = Vg + kt2 * 64 * HDIM;
        float* kd = sh + b * 2 * TILE_F;
        float* vd = kd + TILE_F;
        #pragma unroll
        for (int i = 0; i < 8; i++) {
            const int idx = t + i * 128;
            const int r = idx >> 4, c4 = (idx & 15) * 4;
            cp_async16(smem_u32(kd + r * AST + c4), Kt + r * 64 + c4);
            cp_async16(smem_u32(vd + r * AST + c4), Vt + r * 64 + c4);
        }
    };

    load_tile(0, 0);
    cp_commit();

    const int rowA = qt * 64 + wm + lr;
    const int rowB = rowA + 8;

    for (int kt = 0; kt < ktiles; kt++) {
        const int buf = kt & 1;
        if (kt + 1 < ktiles) {
            load_tile(kt + 1, buf ^ 1);
            cp_commit();
            cp_wait<1>();
        } else {
            cp_wait<0>();
        }
        __syncthreads();

        const float* Ks = sh + buf * 2 * TILE_F;
        const float* Vs = Ks + TILE_F;

        // ---- S = Q @ K^T (16x64 per warp) ----
        float s[8][4];
        #pragma unroll
        for (int nt = 0; nt < 8; nt++)
            #pragma unroll
            for (int qq = 0; qq < 4; qq++) s[nt][qq] = 0.0f;

        #pragma unroll
        for (int ks = 0; ks < 8; ks++) {
            const int kc = ks * 8 + lc;
            #pragma unroll
            for (int nt = 0; nt < 8; nt++) {
                const float* kp = Ks + (nt * 8 + lr) * AST + kc;
                uint32_t b[2] = { __float_as_uint(kp[0]), __float_as_uint(kp[4]) };
                mma8(s[nt], q[ks], b);
            }
        }

        // ---- causal mask (diagonal tile only) ----
        if (kt == qt) {
            const int col0 = kt * 64;
            #pragma unroll
            for (int nt = 0; nt < 8; nt++) {
                const int c0 = col0 + nt * 8 + 2 * lc;
                if (c0 > rowA)     s[nt][0] = -1e30f;
                if (c0 + 1 > rowA) s[nt][1] = -1e30f;
                if (c0 > rowB)     s[nt][2] = -1e30f;
                if (c0 + 1 > rowB) s[nt][3] = -1e30f;
            }
        }

        // ---- online softmax (rows warp-local: quad shuffles) ----
        float tmA = s[0][0], tmB = s[0][2];
        #pragma unroll
        for (int nt = 0; nt < 8; nt++) {
            tmA = fmaxf(tmA, fmaxf(s[nt][0], s[nt][1]));
            tmB = fmaxf(tmB, fmaxf(s[nt][2], s[nt][3]));
        }
        tmA = fmaxf(tmA, __shfl_xor_sync(0xffffffffu, tmA, 1));
        tmA = fmaxf(tmA, __shfl_xor_sync(0xffffffffu, tmA, 2));
        tmB = fmaxf(tmB, __shfl_xor_sync(0xffffffffu, tmB, 1));
        tmB = fmaxf(tmB, __shfl_xor_sync(0xffffffffu, tmB, 2));

        const float nmA = fmaxf(mA, tmA), nmB = fmaxf(mB, tmB);
        const float scA = __expf(mA - nmA), scB = __expf(mB - nmB);
        mA = nmA; mB = nmB;

        float sumA = 0.0f, sumB = 0.0f;
        #pragma unroll
        for (int nt = 0; nt < 8; nt++) {
            s[nt][0] = __expf(s[nt][0] - mA); sumA += s[nt][0];
            s[nt][1] = __expf(s[nt][1] - mA); sumA += s[nt][1];
            s[nt][2] = __expf(s[nt][2] - mB); sumB += s[nt][2];
            s[nt][3] = __expf(s[nt][3] - mB); sumB += s[nt][3];
        }
        sumA += __shfl_xor_sync(0xffffffffu, sumA, 1);
        sumA += __shfl_xor_sync(0xffffffffu, sumA, 2);
        sumB += __shfl_xor_sync(0xffffffffu, sumB, 1);
        sumB += __shfl_xor_sync(0xffffffffu, sumB, 2);
        lA = lA * scA + sumA;
        lB = lB * scB + sumB;

        #pragma unroll
        for (int nt = 0; nt < 8; nt++) {
            o[nt][0] *= scA; o[nt][1] *= scA;
            o[nt][2] *= scB; o[nt][3] *= scB;
        }

        // ---- O += P @ V ; P C-frag -> A-frag via quad shuffles ----
        const int src_lo = (lane & ~3) | (lc >> 1);
        const int src_hi = src_lo + 2;
        const bool odd = (lc & 1);
        #pragma unroll
        for (int ks2 = 0; ks2 < 8; ks2++) {
            const float p0 = s[ks2][0], p1 = s[ks2][1];
            const float p2 = s[ks2][2], p3 = s[ks2][3];
            const float v0l = __shfl_sync(0xffffffffu, p0, src_lo);
            const float v1l = __shfl_sync(0xffffffffu, p1, src_lo);
            const float v0h = __shfl_sync(0xffffffffu, p0, src_hi);
            const float v1h = __shfl_sync(0xffffffffu, p1, src_hi);
            const float w0l = __shfl_sync(0xffffffffu, p2, src_lo);
            const float w1l = __shfl_sync(0xffffffffu, p3, src_lo);
            const float w0h = __shfl_sync(0xffffffffu, p2, src_hi);
            const float w1h = __shfl_sync(0xffffffffu, p3, src_hi);
            uint32_t a[4];
            a[0] = __float_as_uint(odd ? v1l : v0l);
            a[1] = __float_as_uint(odd ? w1l : w0l);
            a[2] = __float_as_uint(odd ? v1h : v0h);
            a[3] = __float_as_uint(odd ? w1h : w0h);

            const float* vp = Vs + (ks2 * 8 + lc) * AST;
            #pragma unroll
            for (int nt = 0; nt < 8; nt++) {
                uint32_t b[2] = { __float_as_uint(vp[nt * 8 + lr]),
                                  __float_as_uint(vp[4 * AST + nt * 8 + lr]) };
                mma8(o[nt], a, b);
            }
        }
        __syncthreads();
    }

    // epilogue: tf32-round so the O projection needs no conversion
    const float invA = 1.0f / lA, invB = 1.0f / lB;
    #pragma unroll
    for (int nt = 0; nt < 8; nt++) {
        const int col = h * HDIM + nt * 8 + 2 * lc;
        float2 va = { f2tf_f(o[nt][0] * invA), f2tf_f(o[nt][1] * invA) };
        float2 vb = { f2tf_f(o[nt][2] * invB), f2tf_f(o[nt][3] * invB) };
        *(float2*)&g_AO[rowA * DMODEL + col] = va;
        *(float2*)&g_AO[rowB * DMODEL + col] = vb;
    }
}

// ---------------------------------------------------------------------------
// Launch
// ---------------------------------------------------------------------------
extern "C" void kernel_launch(void* const* d_in, const int* in_sizes, int n_in,
                              void* d_out, int out_size)
{
    const float* x  = (const float*)d_in[0];
    const float* Wq = (const float*)d_in[1];
    const float* bq = (const float*)d_in[2];
    const float* Wk = (const float*)d_in[3];
    const float* bk = (const float*)d_in[4];
    const float* Wv = (const float*)d_in[5];
    const float* bv = (const float*)d_in[6];
    const float* Wo = (const float*)d_in[7];
    const float* bo = (const float*)d_in[8];
    float* out = (float*)d_out;

    constexpr int SM_QKV = (2 * 128 + 2 * 128) * PB * 4;   // 73728
    constexpr int SM_O   = (2 * 64 + 2 * 128) * PB * 4;    // 55296

    cudaFuncSetAttribute((const void*)proj_tf<0, 128>,
                         cudaFuncAttributeMaxDynamicSharedMemorySize, SM_QKV);
    cudaFuncSetAttribute((const void*)proj_tf<1, 64>,
                         cudaFuncAttributeMaxDynamicSharedMemorySize, SM_O);
    cudaFuncSetAttribute((const void*)attn_tc,
                         cudaFuncAttributeMaxDynamicSharedMemorySize, ATTN_SMEM_BYTES);

    prep_round<<<(PREP_TOTAL + 255) / 256, 256>>>(x, Wq, Wk, Wv, Wo);

    dim3 gq(S_LEN / 128, DMODEL / 128, 3);   // 32 x 6 x 3 = 576
    proj_tf<0, 128><<<gq, 256, SM_QKV>>>(bq, bk, bv, nullptr);

    dim3 ag(S_LEN / 64, NHEADS);             // 64 x 12 = 768
    attn_tc<<<ag, 128, ATTN_SMEM_BYTES>>>();

    dim3 go(S_LEN / 64, DMODEL / 128);       // 64 x 6 = 384
    proj_tf<1, 64><<<go, 256, SM_O>>>(bo, nullptr, nullptr, out);
}

// round 7
// speedup vs baseline: 4.8662x; 1.1099x over previous
#include <cuda_runtime.h>
#include <stdint.h>

#define S_LEN   4096
#define DMODEL  768
#define NHEADS  12
#define HDIM    64
#define WN      (DMODEL * DMODEL)

// ---------------------------------------------------------------------------
// Scratch (device globals)
// ---------------------------------------------------------------------------
__device__ float g_Q[NHEADS * S_LEN * HDIM];   // [H][S][64], pre-scaled 0.125
__device__ float g_K[NHEADS * S_LEN * HDIM];
__device__ float g_V[NHEADS * S_LEN * HDIM];
__device__ float g_AO[S_LEN * DMODEL];         // tf32-rounded attention output
__device__ float g_Xtf[S_LEN * DMODEL];        // tf32-rounded input
__device__ float g_Wt[4 * WN];                 // tf32-rounded Wq,Wk,Wv,Wo

// ---------------------------------------------------------------------------
// Helpers
// ---------------------------------------------------------------------------
__device__ __forceinline__ uint32_t smem_u32(const void* p) {
    return (uint32_t)__cvta_generic_to_shared(p);
}
__device__ __forceinline__ uint32_t f2tf(float x) {
    uint32_t r;
    asm("cvt.rna.tf32.f32 %0, %1;" : "=r"(r) : "f"(x));
    return r;
}
__device__ __forceinline__ float f2tf_f(float x) { return __uint_as_float(f2tf(x)); }

__device__ __forceinline__ void mma8(float c[4], const uint32_t a[4], const uint32_t b[2]) {
    asm volatile(
        "mma.sync.aligned.m16n8k8.row.col.f32.tf32.tf32.f32 "
        "{%0,%1,%2,%3},{%4,%5,%6,%7},{%8,%9},{%0,%1,%2,%3};"
        : "+f"(c[0]), "+f"(c[1]), "+f"(c[2]), "+f"(c[3])
        : "r"(a[0]), "r"(a[1]), "r"(a[2]), "r"(a[3]), "r"(b[0]), "r"(b[1]));
}
__device__ __forceinline__ void cp_async16(uint32_t dst, const void* src) {
    asm volatile("cp.async.cg.shared.global [%0], [%1], 16;" :: "r"(dst), "l"(src));
}
__device__ __forceinline__ void cp_commit() {
    asm volatile("cp.async.commit_group;" ::: "memory");
}
template <int N>
__device__ __forceinline__ void cp_wait() {
    asm volatile("cp.async.wait_group %0;" :: "n"(N) : "memory");
}

// ---------------------------------------------------------------------------
// Prep: tf32-round x -> g_Xtf and Wq/Wk/Wv/Wo -> g_Wt
// ---------------------------------------------------------------------------
#define XN4 (S_LEN * DMODEL / 4)
#define WN4 (WN / 4)
#define PREP_TOTAL (XN4 + 4 * WN4)

__global__ void __launch_bounds__(256)
prep_round(const float* __restrict__ x,  const float* __restrict__ Wq,
           const float* __restrict__ Wk, const float* __restrict__ Wv,
           const float* __restrict__ Wo)
{
    const int i = blockIdx.x * 256 + threadIdx.x;
    if (i >= PREP_TOTAL) return;
    const float* src;
    float* dst;
    int off;
    if (i < XN4) {
        src = x; dst = g_Xtf; off = i;
    } else {
        const int j = i - XN4;
        const int w = j / WN4;
        off = j - w * WN4;
        src = (w == 0) ? Wq : (w == 1) ? Wk : (w == 2) ? Wv : Wo;
        dst = g_Wt + w * WN;
    }
    float4 v = ((const float4*)src)[off];
    v.x = f2tf_f(v.x); v.y = f2tf_f(v.y); v.z = f2tf_f(v.z); v.w = f2tf_f(v.w);
    ((float4*)dst)[off] = v;
}

// ---------------------------------------------------------------------------
// Projection GEMM (tf32, pre-rounded inputs).  C = X @ W^T + bias.
// CTA tile BM x 128, K-step 32, cp.async double-buffered, 256 threads,
// 8 warps (2m x 4n), warp tile (BM/2) x 32.  Single-barrier pipeline.
// OPROJ=0: fused QKV (blockIdx.z selects, head-major store, z==0 scaled).
// OPROJ=1: O projection -> outO [S][768].
// ---------------------------------------------------------------------------
#define PB 36

template <int OPROJ, int BM>
__global__ void __launch_bounds__(256, OPROJ ? 4 : 2)
proj_tf(const float* __restrict__ b0, const float* __restrict__ b1,
        const float* __restrict__ b2, float* __restrict__ outO)
{
    constexpr int MT     = BM / 32;        // m-frags per warp
    constexpr int XTILE  = BM * PB;
    constexpr int WTILE  = 128 * PB;

    extern __shared__ float sh[];
    float* Xs = sh;                        // [2][BM][PB]
    float* Ws = sh + 2 * XTILE;            // [2][128][PB]

    const int t    = threadIdx.x;
    const int lane = t & 31;
    const int wid  = t >> 5;
    const int m0   = blockIdx.x * BM;
    const int n0   = blockIdx.y * 128;
    const int z    = OPROJ ? 3 : blockIdx.z;

    const float* X    = OPROJ ? g_AO : g_Xtf;
    const float* W    = g_Wt + z * WN;
    const float* bias = OPROJ ? b0 : (z == 0 ? b0 : (z == 1 ? b1 : b2));
    float* outH = (z == 0) ? g_Q : (z == 1) ? g_K : g_V;

    const int wm = (wid & 1) * (BM / 2);
    const int wn = (wid >> 1) * 32;
    const int lr = lane >> 2;
    const int lc = lane & 3;

    float c[MT][4][4];
    #pragma unroll
    for (int mt = 0; mt < MT; mt++)
        #pragma unroll
        for (int nt = 0; nt < 4; nt++)
            #pragma unroll
            for (int q = 0; q < 4; q++) c[mt][nt][q] = 0.0f;

    auto load = [&](int kt, int buf) {
        const int k0 = kt * 32;
        #pragma unroll
        for (int i = 0; i < BM / 32; i++) {
            const int e = t + i * 256;
            const int r = e >> 3, c4 = (e & 7) * 4;
            cp_async16(smem_u32(Xs + buf * XTILE + r * PB + c4),
                       X + (m0 + r) * DMODEL + k0 + c4);
        }
        #pragma unroll
        for (int i = 0; i < 4; i++) {
            const int e = t + i * 256;
            const int r = e >> 3, c4 = (e & 7) * 4;
            cp_async16(smem_u32(Ws + buf * WTILE + r * PB + c4),
                       W + (n0 + r) * DMODEL + k0 + c4);
        }
    };

    load(0, 0);
    cp_commit();

    for (int kt = 0; kt < DMODEL / 32; kt++) {
        const int buf = kt & 1;
        cp_wait<0>();
        __syncthreads();
        if (kt + 1 < DMODEL / 32) {
            load(kt + 1, buf ^ 1);
            cp_commit();
        }

        const float* Xb = Xs + buf * XTILE;
        const float* Wb = Ws + buf * WTILE;

        #pragma unroll
        for (int ks = 0; ks < 32; ks += 8) {
            const int kc = ks + lc;
            uint32_t a[MT][4], b[4][2];
            #pragma unroll
            for (int mt = 0; mt < MT; mt++) {
                const float* xp = Xb + (wm + mt * 16 + lr) * PB + kc;
                a[mt][0] = __float_as_uint(xp[0]);
                a[mt][1] = __float_as_uint(xp[8 * PB]);
                a[mt][2] = __float_as_uint(xp[4]);
                a[mt][3] = __float_as_uint(xp[8 * PB + 4]);
            }
            #pragma unroll
            for (int nt = 0; nt < 4; nt++) {
                const float* wp = Wb + (wn + nt * 8 + lr) * PB + kc;
                b[nt][0] = __float_as_uint(wp[0]);
                b[nt][1] = __float_as_uint(wp[4]);
            }
            #pragma unroll
            for (int mt = 0; mt < MT; mt++)
                #pragma unroll
                for (int nt = 0; nt < 4; nt++)
                    mma8(c[mt][nt], a[mt], b[nt]);
        }
    }

    // epilogue
    #pragma unroll
    for (int mt = 0; mt < MT; mt++) {
        #pragma unroll
        for (int nt = 0; nt < 4; nt++) {
            const int col = n0 + wn + nt * 8 + lc * 2;
            const float bx = bias[col], by = bias[col + 1];
            #pragma unroll
            for (int half = 0; half < 2; half++) {
                const int row = m0 + wm + mt * 16 + lr + half * 8;
                float2 v = { c[mt][nt][half * 2 + 0] + bx,
                             c[mt][nt][half * 2 + 1] + by };
                if (!OPROJ) {
                    if (z == 0) { v.x *= 0.125f; v.y *= 0.125f; }
                    *(float2*)&outH[(col >> 6) * (S_LEN * HDIM) + row * HDIM + (col & 63)] = v;
                } else {
                    *(float2*)&outO[row * DMODEL + col] = v;
                }
            }
        }
    }
}

// ---------------------------------------------------------------------------
// Causal flash attention.  BQ=64, BK=64, 128 threads (4 warps x 16 rows).
// K tiles stride 68 (conflict-free K B-frags), V tiles stride 72
// (conflict-free V B-frags: bank = 8*lc + lr).  Single barrier per k-tile;
// Q staged into the V1 buffer so its load overlaps tile-0's load.
// ---------------------------------------------------------------------------
#define KST 68
#define VST 72
#define KTILE (64 * KST)                    // floats
#define VTILE (64 * VST)
#define ATTN_SMEM_BYTES ((2 * KTILE + 2 * VTILE) * 4)   // 71680

__global__ void __launch_bounds__(128, 3)
attn_tc()
{
    extern __shared__ float sh[];
    // layout: K0 | K1 | V0 | V1   (Q staged in V1 region at startup)

    const int h    = blockIdx.y;
    const int qt   = (S_LEN / 64 - 1) - blockIdx.x;   // heavy blocks first
    const int t    = threadIdx.x;
    const int lane = t & 31;
    const int wid  = t >> 5;
    const int wm   = wid * 16;
    const int lr   = lane >> 2;
    const int lc   = lane & 3;

    const float* Qg = g_Q + (h * S_LEN + qt * 64) * HDIM;
    const float* Kg = g_K + h * S_LEN * HDIM;
    const float* Vg = g_V + h * S_LEN * HDIM;

    float* Qstage = sh + 2 * KTILE + VTILE;   // V1 region, used with stride KST

    auto load_tile = [&](int kt2, int b) {
        const float* Kt = Kg + kt2 * 64 * HDIM;
        const float* Vt = Vg + kt2 * 64 * HDIM;
        float* kd = sh + b * KTILE;
        float* vd = sh + 2 * KTILE + b * VTILE;
        #pragma unroll
        for (int i = 0; i < 8; i++) {
            const int idx = t + i * 128;
            const int r = idx >> 4, c4 = (idx & 15) * 4;
            cp_async16(smem_u32(kd + r * KST + c4), Kt + r * 64 + c4);
            cp_async16(smem_u32(vd + r * VST + c4), Vt + r * 64 + c4);
        }
    };

    // ---- stage Q into V1 region; overlap with tile-0 K/V load ----
    #pragma unroll
    for (int i = 0; i < 8; i++) {
        const int idx = t + i * 128;
        const int r = idx >> 4, c4 = (idx & 15) * 4;
        cp_async16(smem_u32(Qstage + r * KST + c4), Qg + r * 64 + c4);
    }
    cp_commit();
    load_tile(0, 0);
    cp_commit();

    cp_wait<1>();          // Q complete (tile-0 load may still be in flight)
    __syncthreads();

    uint32_t q[8][4];
    {
        const float* Qrow = Qstage + (wm + lr) * KST;
        #pragma unroll
        for (int ks = 0; ks < 8; ks++) {
            const int kc = ks * 8 + lc;
            q[ks][0] = __float_as_uint(Qrow[kc]);
            q[ks][1] = __float_as_uint(Qrow[8 * KST + kc]);
            q[ks][2] = __float_as_uint(Qrow[kc + 4]);
            q[ks][3] = __float_as_uint(Qrow[8 * KST + kc + 4]);
        }
    }
    // No extra barrier: load(1) (which overwrites V1/Q) is only issued after
    // the t=0 iteration's __syncthreads below, which every warp reaches only
    // after finishing these register reads.

    float o[8][4];
    #pragma unroll
    for (int nt = 0; nt < 8; nt++)
        #pragma unroll
        for (int qq = 0; qq < 4; qq++) o[nt][qq] = 0.0f;
    float mA = -1e30f, mB = -1e30f, lA = 0.0f, lB = 0.0f;

    const int ktiles = qt + 1;
    const int rowA = qt * 64 + wm + lr;
    const int rowB = rowA + 8;

    for (int kt = 0; kt < ktiles; kt++) {
        const int buf = kt & 1;
        cp_wait<0>();
        __syncthreads();   // buffer kt ready AND everyone done with buf from kt-2
        if (kt + 1 < ktiles) {
            load_tile(kt + 1, buf ^ 1);
            cp_commit();
        }

        const float* Ks = sh + buf * KTILE;
        const float* Vs = sh + 2 * KTILE + buf * VTILE;

        // ---- S = Q @ K^T (16x64 per warp) ----
        float s[8][4];
        #pragma unroll
        for (int nt = 0; nt < 8; nt++)
            #pragma unroll
            for (int qq = 0; qq < 4; qq++) s[nt][qq] = 0.0f;

        #pragma unroll
        for (int ks = 0; ks < 8; ks++) {
            const int kc = ks * 8 + lc;
            #pragma unroll
            for (int nt = 0; nt < 8; nt++) {
                const float* kp = Ks + (nt * 8 + lr) * KST + kc;
                uint32_t b[2] = { __float_as_uint(kp[0]), __float_as_uint(kp[4]) };
                mma8(s[nt], q[ks], b);
            }
        }

        // ---- causal mask (diagonal tile only) ----
        if (kt == qt) {
            const int col0 = kt * 64;
            #pragma unroll
            for (int nt = 0; nt < 8; nt++) {
                const int c0 = col0 + nt * 8 + 2 * lc;
                if (c0 > rowA)     s[nt][0] = -1e30f;
                if (c0 + 1 > rowA) s[nt][1] = -1e30f;
                if (c0 > rowB)     s[nt][2] = -1e30f;
                if (c0 + 1 > rowB) s[nt][3] = -1e30f;
            }
        }

        // ---- online softmax (rows warp-local: quad shuffles) ----
        float tmA = s[0][0], tmB = s[0][2];
        #pragma unroll
        for (int nt = 0; nt < 8; nt++) {
            tmA = fmaxf(tmA, fmaxf(s[nt][0], s[nt][1]));
            tmB = fmaxf(tmB, fmaxf(s[nt][2], s[nt][3]));
        }
        tmA = fmaxf(tmA, __shfl_xor_sync(0xffffffffu, tmA, 1));
        tmA = fmaxf(tmA, __shfl_xor_sync(0xffffffffu, tmA, 2));
        tmB = fmaxf(tmB, __shfl_xor_sync(0xffffffffu, tmB, 1));
        tmB = fmaxf(tmB, __shfl_xor_sync(0xffffffffu, tmB, 2));

        const float nmA = fmaxf(mA, tmA), nmB = fmaxf(mB, tmB);
        const float scA = __expf(mA - nmA), scB = __expf(mB - nmB);
        mA = nmA; mB = nmB;

        float sumA = 0.0f, sumB = 0.0f;
        #pragma unroll
        for (int nt = 0; nt < 8; nt++) {
            s[nt][0] = __expf(s[nt][0] - mA); sumA += s[nt][0];
            s[nt][1] = __expf(s[nt][1] - mA); sumA += s[nt][1];
            s[nt][2] = __expf(s[nt][2] - mB); sumB += s[nt][2];
            s[nt][3] = __expf(s[nt][3] - mB); sumB += s[nt][3];
        }
        sumA += __shfl_xor_sync(0xffffffffu, sumA, 1);
        sumA += __shfl_xor_sync(0xffffffffu, sumA, 2);
        sumB += __shfl_xor_sync(0xffffffffu, sumB, 1);
        sumB += __shfl_xor_sync(0xffffffffu, sumB, 2);
        lA = lA * scA + sumA;
        lB = lB * scB + sumB;

        #pragma unroll
        for (int nt = 0; nt < 8; nt++) {
            o[nt][0] *= scA; o[nt][1] *= scA;
            o[nt][2] *= scB; o[nt][3] *= scB;
        }

        // ---- O += P @ V ; P C-frag -> A-frag via quad shuffles ----
        const int src_lo = (lane & ~3) | (lc >> 1);
        const int src_hi = src_lo + 2;
        const bool odd = (lc & 1);
        #pragma unroll
        for (int ks2 = 0; ks2 < 8; ks2++) {
            const float p0 = s[ks2][0], p1 = s[ks2][1];
            const float p2 = s[ks2][2], p3 = s[ks2][3];
            const float v0l = __shfl_sync(0xffffffffu, p0, src_lo);
            const float v1l = __shfl_sync(0xffffffffu, p1, src_lo);
            const float v0h = __shfl_sync(0xffffffffu, p0, src_hi);
            const float v1h = __shfl_sync(0xffffffffu, p1, src_hi);
            const float w0l = __shfl_sync(0xffffffffu, p2, src_lo);
            const float w1l = __shfl_sync(0xffffffffu, p3, src_lo);
            const float w0h = __shfl_sync(0xffffffffu, p2, src_hi);
            const float w1h = __shfl_sync(0xffffffffu, p3, src_hi);
            uint32_t a[4];
            a[0] = __float_as_uint(odd ? v1l : v0l);
            a[1] = __float_as_uint(odd ? w1l : w0l);
            a[2] = __float_as_uint(odd ? v1h : v0h);
            a[3] = __float_as_uint(odd ? w1h : w0h);

            const float* vp = Vs + (ks2 * 8 + lc) * VST;
            #pragma unroll
            for (int nt = 0; nt < 8; nt++) {
                uint32_t b[2] = { __float_as_uint(vp[nt * 8 + lr]),
                                  __float_as_uint(vp[4 * VST + nt * 8 + lr]) };
                mma8(o[nt], a, b);
            }
        }
    }

    // epilogue: tf32-round so the O projection needs no conversion
    const float invA = 1.0f / lA, invB = 1.0f / lB;
    #pragma unroll
    for (int nt = 0; nt < 8; nt++) {
        const int col = h * HDIM + nt * 8 + 2 * lc;
        float2 va = { f2tf_f(o[nt][0] * invA), f2tf_f(o[nt][1] * invA) };
        float2 vb = { f2tf_f(o[nt][2] * invB), f2tf_f(o[nt][3] * invB) };
        *(float2*)&g_AO[rowA * DMODEL + col] = va;
        *(float2*)&g_AO[rowB * DMODEL + col] = vb;
    }
}

// ---------------------------------------------------------------------------
// Launch
// ---------------------------------------------------------------------------
extern "C" void kernel_launch(void* const* d_in, const int* in_sizes, int n_in,
                              void* d_out, int out_size)
{
    const float* x  = (const float*)d_in[0];
    const float* Wq = (const float*)d_in[1];
    const float* bq = (const float*)d_in[2];
    const float* Wk = (const float*)d_in[3];
    const float* bk = (const float*)d_in[4];
    const float* Wv = (const float*)d_in[5];
    const float* bv = (const float*)d_in[6];
    const float* Wo = (const float*)d_in[7];
    const float* bo = (const float*)d_in[8];
    float* out = (float*)d_out;

    constexpr int SM_QKV = (2 * 128 + 2 * 128) * PB * 4;   // 73728
    constexpr int SM_O   = (2 * 64 + 2 * 128) * PB * 4;    // 55296

    cudaFuncSetAttribute((const void*)proj_tf<0, 128>,
                         cudaFuncAttributeMaxDynamicSharedMemorySize, SM_QKV);
    cudaFuncSetAttribute((const void*)proj_tf<1, 64>,
                         cudaFuncAttributeMaxDynamicSharedMemorySize, SM_O);
    cudaFuncSetAttribute((const void*)attn_tc,
                         cudaFuncAttributeMaxDynamicSharedMemorySize, ATTN_SMEM_BYTES);

    prep_round<<<(PREP_TOTAL + 255) / 256, 256>>>(x, Wq, Wk, Wv, Wo);

    dim3 gq(S_LEN / 128, DMODEL / 128, 3);   // 32 x 6 x 3 = 576
    proj_tf<0, 128><<<gq, 256, SM_QKV>>>(bq, bk, bv, nullptr);

    dim3 ag(S_LEN / 64, NHEADS);             // 64 x 12 = 768
    attn_tc<<<ag, 128, ATTN_SMEM_BYTES>>>();

    dim3 go(S_LEN / 64, DMODEL / 128);       // 64 x 6 = 384
    proj_tf<1, 64><<<go, 256, SM_O>>>(bo, nullptr, nullptr, out);
}